// round 2
// baseline (speedup 1.0000x reference)
#include <cuda_runtime.h>
#include <math.h>

#define BB 64
#define TT 512
#define VV 256
#define MEM 1024
#define G4 4096

// ---------------- device scratch (no allocation allowed) ----------------
__device__ float g_Zx[(size_t)TT * BB * G4];          // 512 MB precomputed input-side z (+bias), gate-permuted
__device__ float g_hall[(size_t)TT * BB * MEM];       // per-layer h sequence (reused)
__device__ float g_c[2][BB * MEM];                    // cell state per layer
__device__ float g_h2[2][2][BB * MEM];                // h state per layer, double-buffered
__device__ float g_W0p[(VV + MEM) * G4];              // W0 with gate-permuted columns
__device__ float g_W1p[(2 * MEM) * G4];               // W1 with gate-permuted columns
__device__ float g_b0p[G4];
__device__ float g_b1p[G4];
__device__ volatile int g_arrive[128];                // grid-barrier flags

__device__ __forceinline__ float sigm(float x) { return 1.0f / (1.0f + expf(-x)); }

// ---------------- init: unpack states, reset barrier flags ----------------
__global__ void init_state(const float* __restrict__ s0, const float* __restrict__ s1) {
    int i = blockIdx.x * 256 + threadIdx.x;            // 0 .. B*MEM-1
    int b = i / MEM, u = i % MEM;
    g_c[0][i] = s0[b * 2 * MEM + u];
    g_h2[0][0][i] = s0[b * 2 * MEM + MEM + u];
    g_c[1][i] = s1[b * 2 * MEM + u];
    g_h2[1][0][i] = s1[b * 2 * MEM + MEM + u];
    if (blockIdx.x == 0 && threadIdx.x < 128) g_arrive[threadIdx.x] = 0;
}

// ---------------- permute W columns: out col u*4+g <- in col g*1024+u ----------------
__global__ void permute_w(const float* __restrict__ W0, const float* __restrict__ b0,
                          const float* __restrict__ W1, const float* __restrict__ b1) {
    size_t i = (size_t)blockIdx.x * 256 + threadIdx.x;
    const size_t n0 = (size_t)(VV + MEM) * G4;
    const size_t n1 = (size_t)(2 * MEM) * G4;
    if (i < n0) {
        int c = (int)(i & 4095); size_t r = i >> 12;
        g_W0p[i] = W0[r * G4 + (size_t)((c & 3) * 1024 + (c >> 2))];
    } else if (i < n0 + n1) {
        size_t k = i - n0;
        int c = (int)(k & 4095); size_t r = k >> 12;
        g_W1p[k] = W1[r * G4 + (size_t)((c & 3) * 1024 + (c >> 2))];
    }
    if (i < G4) {
        int c = (int)i;
        g_b0p[c] = b0[(c & 3) * 1024 + (c >> 2)];
        g_b1p[c] = b1[(c & 3) * 1024 + (c >> 2)];
    }
}

// ---------------- big parallel GEMM: C[r,n] = bias[n] + sum_k A(r)[k]*W[k,n] ----------------
// r = t*64 + b ; A row addr = A + b*sb + t*st ; C addr = b*ocb + t*oct + n
__global__ __launch_bounds__(256) void gemm_big(
    const float* __restrict__ Ain, long sb, long st,
    const float* __restrict__ Wext, const float* __restrict__ bext,
    float* __restrict__ Cout, long ocb, long oct,
    int N, int K, int src_gh, int dst_gz, int w_sel)
{
    const float* A = src_gh ? (const float*)g_hall : Ain;
    float* C = dst_gz ? (float*)g_Zx : Cout;
    const float* W = (w_sel == 0) ? g_W0p : ((w_sel == 1) ? g_W1p : Wext);
    const float* bias = (w_sel == 0) ? g_b0p : ((w_sel == 1) ? g_b1p : bext);

    __shared__ float As[8][128];
    __shared__ float Bs[8][128];

    int tid = threadIdx.x;
    int brow = blockIdx.y * 128;
    int bcol = blockIdx.x * 128;
    int ty = tid >> 4;
    int tx = tid & 15;
    int arow = tid >> 1;
    int ak   = (tid & 1) * 4;
    int bk   = tid >> 5;
    int bn   = (tid & 31) * 4;

    long r = brow + arow;
    const float* Arow = A + (r & 63) * sb + (r >> 6) * st;
    const float* Wp0 = W + (long)bk * N + bcol + bn;

    float acc[8][8];
#pragma unroll
    for (int i = 0; i < 8; i++)
#pragma unroll
        for (int j = 0; j < 8; j++) acc[i][j] = 0.0f;

    for (int k0 = 0; k0 < K; k0 += 8) {
        float4 av = *(const float4*)(Arow + k0 + ak);
        As[ak + 0][arow] = av.x;
        As[ak + 1][arow] = av.y;
        As[ak + 2][arow] = av.z;
        As[ak + 3][arow] = av.w;
        *(float4*)&Bs[bk][bn] = *(const float4*)(Wp0 + (long)k0 * N);
        __syncthreads();
#pragma unroll
        for (int k = 0; k < 8; k++) {
            float4 a0 = *(const float4*)&As[k][ty * 8];
            float4 a1 = *(const float4*)&As[k][ty * 8 + 4];
            float4 b0 = *(const float4*)&Bs[k][tx * 8];
            float4 b1 = *(const float4*)&Bs[k][tx * 8 + 4];
            float af[8] = {a0.x, a0.y, a0.z, a0.w, a1.x, a1.y, a1.z, a1.w};
            float bf[8] = {b0.x, b0.y, b0.z, b0.w, b1.x, b1.y, b1.z, b1.w};
#pragma unroll
            for (int i = 0; i < 8; i++)
#pragma unroll
                for (int j = 0; j < 8; j++) acc[i][j] += af[i] * bf[j];
        }
        __syncthreads();
    }

#pragma unroll
    for (int i = 0; i < 8; i++) {
        long r2 = brow + ty * 8 + i;
        long co = (r2 & 63) * ocb + (r2 >> 6) * oct + bcol;
#pragma unroll
        for (int j = 0; j < 8; j++)
            C[co + tx * 8 + j] = acc[i][j] + bias[bcol + tx * 8 + j];
    }
}

// ---------------- persistent recurrence: one kernel per layer, 512 steps inside ----------------
// 128 blocks x 256 threads; block owns units [bid*8, bid*8+8) = permuted cols [bid*32, bid*32+32).
// Per step: z_rec[64x32] = h[64x1024] @ Wh[:, slice] (full K, double-buffered smem tiles),
// add g_Zx, gate math, write h to the other h buffer, flag-array grid barrier.
__global__ __launch_bounds__(256) void lstm_layer_persist(int layer, int ep_base)
{
    const float* Wh = (layer == 0) ? (g_W0p + (size_t)VV * G4)
                                   : (g_W1p + (size_t)MEM * G4);
    float* c_st = g_c[layer];
    const int bid = blockIdx.x;
    const int tid = threadIdx.x;
    const int n0 = bid * 32;

    __shared__ float As[2][16][72];   // [buf][k][row] padded
    __shared__ float Bs[2][16][34];   // [buf][k][col] padded
    __shared__ float Zs[64][33];      // z tile for pointwise

    const int tx = tid & 15;          // col/2
    const int ty = tid >> 4;          // row/4
    const int la_row = tid >> 2;      // 0..63
    const int la_k   = (tid & 3) * 4; // 0,4,8,12
    const int lw_k   = tid >> 4;      // 0..15
    const int lw_c   = (tid & 15) * 2;

    for (int t = 0; t < TT; t++) {
        const float* hr = g_h2[layer][t & 1];
        float* hw = g_h2[layer][(t + 1) & 1];

        float acc[4][2];
#pragma unroll
        for (int i = 0; i < 4; i++) { acc[i][0] = 0.0f; acc[i][1] = 0.0f; }

        // prefetch tile 0 (L2 reads: bypass L1, other SMs wrote h)
        float4 pa = __ldcg((const float4*)(hr + la_row * MEM + la_k));
        float2 pw = *(const float2*)(Wh + (size_t)lw_k * G4 + n0 + lw_c);
        As[0][la_k + 0][la_row] = pa.x;
        As[0][la_k + 1][la_row] = pa.y;
        As[0][la_k + 2][la_row] = pa.z;
        As[0][la_k + 3][la_row] = pa.w;
        Bs[0][lw_k][lw_c] = pw.x;
        Bs[0][lw_k][lw_c + 1] = pw.y;

        for (int k0 = 0; k0 < 64; k0++) {
            __syncthreads();
            int cur = k0 & 1;
            if (k0 < 63) {
                pa = __ldcg((const float4*)(hr + la_row * MEM + (k0 + 1) * 16 + la_k));
                pw = *(const float2*)(Wh + (size_t)((k0 + 1) * 16 + lw_k) * G4 + n0 + lw_c);
            }
#pragma unroll
            for (int k = 0; k < 16; k++) {
                float4 a = *(const float4*)&As[cur][k][ty * 4];
                float2 b = *(const float2*)&Bs[cur][k][tx * 2];
                acc[0][0] += a.x * b.x; acc[0][1] += a.x * b.y;
                acc[1][0] += a.y * b.x; acc[1][1] += a.y * b.y;
                acc[2][0] += a.z * b.x; acc[2][1] += a.z * b.y;
                acc[3][0] += a.w * b.x; acc[3][1] += a.w * b.y;
            }
            if (k0 < 63) {
                int nxt = cur ^ 1;
                As[nxt][la_k + 0][la_row] = pa.x;
                As[nxt][la_k + 1][la_row] = pa.y;
                As[nxt][la_k + 2][la_row] = pa.z;
                As[nxt][la_k + 3][la_row] = pa.w;
                Bs[nxt][lw_k][lw_c] = pw.x;
                Bs[nxt][lw_k][lw_c + 1] = pw.y;
            }
        }

        // stage z tile to smem
#pragma unroll
        for (int i = 0; i < 4; i++) {
            Zs[ty * 4 + i][tx * 2]     = acc[i][0];
            Zs[ty * 4 + i][tx * 2 + 1] = acc[i][1];
        }
        __syncthreads();

        // pointwise: 512 elems (64 batch x 8 units), 2 per thread
#pragma unroll
        for (int e = tid; e < 512; e += 256) {
            int m = e >> 3, j = e & 7;
            size_t zb = (size_t)t * BB * G4 + (size_t)m * G4 + n0 + j * 4;
            float zi = Zs[m][j * 4 + 0] + g_Zx[zb + 0];
            float zj = Zs[m][j * 4 + 1] + g_Zx[zb + 1];
            float zf = Zs[m][j * 4 + 2] + g_Zx[zb + 2];
            float zo = Zs[m][j * 4 + 3] + g_Zx[zb + 3];
            int ci = m * MEM + bid * 8 + j;
            float c = c_st[ci];
            float cn = c * sigm(zf + 1.0f) + sigm(zi) * tanhf(zj);
            float hn = tanhf(cn) * sigm(zo);
            c_st[ci] = cn;
            hw[ci] = hn;
            g_hall[(size_t)t * BB * MEM + ci] = hn;
        }

        // grid barrier: per-block flag write + all-flag poll
        __syncthreads();
        int want = ep_base + t + 1;
        if (tid == 0) {
            __threadfence();
            g_arrive[bid] = want;
        }
        if (tid < 128) {
            while (g_arrive[tid] < want) { }
        }
        __syncthreads();
        __threadfence();   // order the poll loads before next step's h loads
    }
}

// ---------------- pack final_state [2, B, 2*MEM] ----------------
__global__ void state_pack(float* __restrict__ out)
{
    int i = blockIdx.x * 256 + threadIdx.x;     // 0 .. 2*B*2*MEM-1
    int l = i / (BB * 2 * MEM);
    int rem = i % (BB * 2 * MEM);
    int b = rem / (2 * MEM);
    int u = rem % (2 * MEM);
    out[i] = (u < MEM) ? g_c[l][b * MEM + u] : g_h2[l][0][b * MEM + (u - MEM)];
}

extern "C" void kernel_launch(void* const* d_in, const int* in_sizes, int n_in,
                              void* d_out, int out_size)
{
    const float* x    = (const float*)d_in[0];
    const float* s0   = (const float*)d_in[1];
    const float* s1   = (const float*)d_in[2];
    const float* W0   = (const float*)d_in[3];
    const float* b0   = (const float*)d_in[4];
    const float* W1   = (const float*)d_in[5];
    const float* b1   = (const float*)d_in[6];
    const float* Wout = (const float*)d_in[7];
    const float* bout = (const float*)d_in[8];
    float* out = (float*)d_out;

    init_state<<<256, 256>>>(s0, s1);

    // permute W0/W1 columns into gate-interleaved layout
    {
        size_t total = (size_t)(VV + MEM) * G4 + (size_t)(2 * MEM) * G4;
        int blocks = (int)((total + 255) / 256);
        permute_w<<<blocks, 256>>>(W0, b0, W1, b1);
    }

    // Phase 1: Zx = x @ W0p[:256,:] + b0p   (M=32768, N=4096, K=256)
    dim3 g1(4096 / 128, (TT * BB) / 128);
    gemm_big<<<g1, 256>>>(x, (long)TT * VV, (long)VV,
                          nullptr, nullptr, nullptr,
                          4096L, (long)BB * 4096, 4096, 256, 0, 1, 0);

    // Layer 0 recurrence: one persistent kernel, 512 steps
    lstm_layer_persist<<<128, 256>>>(0, 0);

    // Phase 3: Zx = h0_all @ W1p[:1024,:] + b1p   (M=32768, N=4096, K=1024)
    gemm_big<<<g1, 256>>>(nullptr, 1024L, (long)BB * MEM,
                          nullptr, nullptr, nullptr,
                          4096L, (long)BB * 4096, 4096, 1024, 1, 1, 1);

    // Layer 1 recurrence
    lstm_layer_persist<<<128, 256>>>(1, TT);

    // Phase 5: out[b,t,:] = h1_all[t,b,:] @ W_out + b_out   (M=32768, N=256, K=1024)
    dim3 g5(256 / 128, (TT * BB) / 128);
    gemm_big<<<g5, 256>>>(nullptr, 1024L, (long)BB * MEM,
                          Wout, bout, out,
                          (long)TT * VV, (long)VV, 256, 1024, 1, 0, 2);

    state_pack<<<1024, 256>>>(out + (long)BB * TT * VV);
}

// round 4
// speedup vs baseline: 2.2529x; 2.2529x over previous
#include <cuda_runtime.h>
#include <math.h>
#include <stdint.h>

#define BB 64
#define TT 512
#define VV 256
#define MEM 1024
#define G4 4096

// ---------------- device scratch (no allocation allowed) ----------------
__device__ float g_Zx[(size_t)TT * BB * G4];          // input-side z (+bias), gate-permuted cols
__device__ float g_hall[(size_t)TT * BB * MEM];       // per-layer h sequence (reused)
__device__ float g_c[2][BB * MEM];                    // cell state per layer
__device__ float g_h2[2][2][BB * MEM];                // h state per layer, double-buffered
__device__ float g_W0p[(VV + MEM) * G4];              // W0, gate-permuted cols, K-major, tf32 (recurrence)
__device__ float g_W1p[(2 * MEM) * G4];               // W1, gate-permuted cols, K-major, tf32 (recurrence)
__device__ float g_W0t[(size_t)G4 * (VV + MEM)];      // W0^T [n][k], gate-permuted n, tf32
__device__ float g_W1t[(size_t)G4 * (2 * MEM)];       // W1^T [n][k], tf32
__device__ float g_b0p[G4];
__device__ float g_b1p[G4];
__device__ volatile int g_arrive[128];                // grid-barrier flags

__device__ __forceinline__ float sigm(float x) { return 1.0f / (1.0f + expf(-x)); }
__device__ __forceinline__ float to_tf32(float x) {
    float r; asm("cvt.rna.tf32.f32 %0, %1;" : "=f"(r) : "f"(x)); return r;
}
__device__ __forceinline__ uint32_t fu(float x) { return __float_as_uint(x); }

// m16n8k8 tf32 mma: D += A(16x8, row) * B(8x8, col). d/c fp32.
__device__ __forceinline__ void mma8(float* d, uint32_t a0, uint32_t a1, uint32_t a2, uint32_t a3,
                                     uint32_t b0, uint32_t b1) {
    asm volatile("mma.sync.aligned.m16n8k8.row.col.f32.tf32.tf32.f32 "
                 "{%0,%1,%2,%3}, {%4,%5,%6,%7}, {%8,%9}, {%0,%1,%2,%3};"
                 : "+f"(d[0]), "+f"(d[1]), "+f"(d[2]), "+f"(d[3])
                 : "r"(a0), "r"(a1), "r"(a2), "r"(a3), "r"(b0), "r"(b1));
}

// ---------------- init ----------------
__global__ void init_state(const float* __restrict__ s0, const float* __restrict__ s1) {
    int i = blockIdx.x * 256 + threadIdx.x;
    int b = i / MEM, u = i % MEM;
    g_c[0][i] = s0[b * 2 * MEM + u];
    g_h2[0][0][i] = s0[b * 2 * MEM + MEM + u];
    g_c[1][i] = s1[b * 2 * MEM + u];
    g_h2[1][0][i] = s1[b * 2 * MEM + MEM + u];
    if (blockIdx.x == 0 && threadIdx.x < 128) g_arrive[threadIdx.x] = 0;
}

// ---------------- K-major gate-permuted tf32 weights (recurrence) + permuted biases ----------------
__global__ void permute_w(const float* __restrict__ W0, const float* __restrict__ b0,
                          const float* __restrict__ W1, const float* __restrict__ b1) {
    size_t i = (size_t)blockIdx.x * 256 + threadIdx.x;
    const size_t n0 = (size_t)(VV + MEM) * G4;
    const size_t n1 = (size_t)(2 * MEM) * G4;
    if (i < n0) {
        int c = (int)(i & 4095); size_t r = i >> 12;
        g_W0p[i] = to_tf32(W0[r * G4 + (size_t)((c & 3) * 1024 + (c >> 2))]);
    } else if (i < n0 + n1) {
        size_t k = i - n0;
        int c = (int)(k & 4095); size_t r = k >> 12;
        g_W1p[k] = to_tf32(W1[r * G4 + (size_t)((c & 3) * 1024 + (c >> 2))]);
    }
    if (i < G4) {
        int c = (int)i;
        g_b0p[c] = b0[(c & 3) * 1024 + (c >> 2)];
        g_b1p[c] = b1[(c & 3) * 1024 + (c >> 2)];
    }
}

// ---------------- transposed tf32 weights WT[n][k] for phase GEMMs ----------------
__global__ __launch_bounds__(256) void transpose_w2(const float* __restrict__ W, int sel) {
    __shared__ float s[32][33];
    int tx = threadIdx.x & 31, ty = threadIdx.x >> 5;   // ty 0..7
    int k0 = blockIdx.x * 32, c0 = blockIdx.y * 32;
    float* dst = (sel == 0) ? g_W0t : g_W1t;
    long wst = (sel == 0) ? (VV + MEM) : (2 * MEM);
#pragma unroll
    for (int j = 0; j < 4; j++)
        s[ty + j * 8][tx] = W[(size_t)(k0 + ty + j * 8) * G4 + c0 + tx];
    __syncthreads();
#pragma unroll
    for (int j = 0; j < 4; j++) {
        int c = c0 + ty + j * 8;
        int n = (c & 1023) * 4 + (c >> 10);
        dst[(size_t)n * wst + k0 + tx] = to_tf32(s[tx][ty + j * 8]);
    }
}

// ---------------- phase GEMM (tf32 mma.sync): g_Zx[r, bcol..] = bias + A[r,:K] @ W[:K, bcol..] ----------------
// block tile 128x64, 8 warps (4m x 2n) of 32x32, Kc=32, XOR-swizzled smem.
__global__ __launch_bounds__(256) void gemm_mma(
    const float* __restrict__ Ain, long sb, long st,
    long wstride, int K, int src_gh, int w_sel)
{
    const float* A = src_gh ? (const float*)g_hall : Ain;
    const float* WT = (w_sel == 0) ? g_W0t : g_W1t;
    const float* bias = (w_sel == 0) ? g_b0p : g_b1p;
    float* C = (float*)g_Zx;

    __shared__ float As[128 * 32];   // [row][k^swz]
    __shared__ float Bs[64 * 32];    // [n][k^swz]

    const int tid = threadIdx.x;
    const int wid = tid >> 5, lane = tid & 31;
    const int gid = lane >> 2, tig = lane & 3;
    const int wm = wid & 3, wn = wid >> 2;
    const long brow = (long)blockIdx.y * 128;
    const int bcol = blockIdx.x * 64;

    // staging maps
    int a_row[4], a_sw[4];
    const float* a_ptr[4];
#pragma unroll
    for (int i = 0; i < 4; i++) {
        int f = tid + i * 256;
        int row = f >> 3, k4 = f & 7;
        a_row[i] = row;
        a_sw[i] = row * 32 + ((k4 * 4) ^ ((row & 7) * 4));
        long r = brow + row;
        a_ptr[i] = A + (r & 63) * sb + (r >> 6) * st + k4 * 4;
    }
    int b_sw[2];
    const float* b_ptr[2];
#pragma unroll
    for (int i = 0; i < 2; i++) {
        int f = tid + i * 256;
        int n = f >> 3, k4 = f & 7;
        b_sw[i] = n * 32 + ((k4 * 4) ^ ((n & 7) * 4));
        b_ptr[i] = WT + (size_t)(bcol + n) * wstride + k4 * 4;
    }

    float acc[2][4][4];
#pragma unroll
    for (int mt = 0; mt < 2; mt++)
#pragma unroll
        for (int nt = 0; nt < 4; nt++)
#pragma unroll
            for (int q = 0; q < 4; q++) acc[mt][nt][q] = 0.0f;

    const int arow0 = wm * 32 + gid;
    const int nb0 = wn * 32 + gid;

    for (int kb = 0; kb < K; kb += 32) {
        float4 av[4], bv[2];
#pragma unroll
        for (int i = 0; i < 4; i++) av[i] = *(const float4*)(a_ptr[i] + kb);
#pragma unroll
        for (int i = 0; i < 2; i++) bv[i] = *(const float4*)(b_ptr[i] + kb);
        __syncthreads();
#pragma unroll
        for (int i = 0; i < 4; i++) {
            float4 v = av[i];
            v.x = to_tf32(v.x); v.y = to_tf32(v.y); v.z = to_tf32(v.z); v.w = to_tf32(v.w);
            *(float4*)&As[a_sw[i]] = v;
        }
#pragma unroll
        for (int i = 0; i < 2; i++) *(float4*)&Bs[b_sw[i]] = bv[i];
        __syncthreads();

#pragma unroll
        for (int kk = 0; kk < 4; kk++) {
            int kx0 = (kk * 8 + tig) ^ (gid * 4);
            int kx1 = (kk * 8 + tig + 4) ^ (gid * 4);
            uint32_t a[2][4];
#pragma unroll
            for (int mt = 0; mt < 2; mt++) {
                int r0 = arow0 + mt * 16;
                a[mt][0] = fu(As[r0 * 32 + kx0]);
                a[mt][1] = fu(As[(r0 + 8) * 32 + kx0]);
                a[mt][2] = fu(As[r0 * 32 + kx1]);
                a[mt][3] = fu(As[(r0 + 8) * 32 + kx1]);
            }
#pragma unroll
            for (int nt = 0; nt < 4; nt++) {
                int n = nb0 + nt * 8;
                uint32_t b0 = fu(Bs[n * 32 + kx0]);
                uint32_t b1 = fu(Bs[n * 32 + kx1]);
#pragma unroll
                for (int mt = 0; mt < 2; mt++)
                    mma8(acc[mt][nt], a[mt][0], a[mt][1], a[mt][2], a[mt][3], b0, b1);
            }
        }
        __syncthreads();
    }

    // epilogue: bias + store
#pragma unroll
    for (int mt = 0; mt < 2; mt++) {
        long r2 = brow + wm * 32 + mt * 16 + gid;
#pragma unroll
        for (int nt = 0; nt < 4; nt++) {
            int col = bcol + wn * 32 + nt * 8 + tig * 2;
            float bz0 = bias[col], bz1 = bias[col + 1];
            float2 v0 = { acc[mt][nt][0] + bz0, acc[mt][nt][1] + bz1 };
            float2 v1 = { acc[mt][nt][2] + bz0, acc[mt][nt][3] + bz1 };
            *(float2*)(C + (size_t)r2 * G4 + col) = v0;
            *(float2*)(C + (size_t)(r2 + 8) * G4 + col) = v1;
        }
    }
}

// ---------------- scalar fp32 GEMM (phase 5: output projection) ----------------
__global__ __launch_bounds__(256) void gemm_big(
    long sb, long st,
    const float* __restrict__ W, const float* __restrict__ bias,
    float* __restrict__ C, long ocb, long oct,
    int N, int K)
{
    const float* A = (const float*)g_hall;
    __shared__ float As[8][128];
    __shared__ float Bs[8][128];

    int tid = threadIdx.x;
    int brow = blockIdx.y * 128;
    int bcol = blockIdx.x * 128;
    int ty = tid >> 4;
    int tx = tid & 15;
    int arow = tid >> 1;
    int ak = (tid & 1) * 4;
    int bk = tid >> 5;
    int bn = (tid & 31) * 4;

    long r = brow + arow;
    const float* Arow = A + (r & 63) * sb + (r >> 6) * st;
    const float* Wp0 = W + (long)bk * N + bcol + bn;

    float acc[8][8];
#pragma unroll
    for (int i = 0; i < 8; i++)
#pragma unroll
        for (int j = 0; j < 8; j++) acc[i][j] = 0.0f;

    for (int k0 = 0; k0 < K; k0 += 8) {
        float4 av = *(const float4*)(Arow + k0 + ak);
        As[ak + 0][arow] = av.x;
        As[ak + 1][arow] = av.y;
        As[ak + 2][arow] = av.z;
        As[ak + 3][arow] = av.w;
        *(float4*)&Bs[bk][bn] = *(const float4*)(Wp0 + (long)k0 * N);
        __syncthreads();
#pragma unroll
        for (int k = 0; k < 8; k++) {
            float4 a0 = *(const float4*)&As[k][ty * 8];
            float4 a1 = *(const float4*)&As[k][ty * 8 + 4];
            float4 b0 = *(const float4*)&Bs[k][tx * 8];
            float4 b1 = *(const float4*)&Bs[k][tx * 8 + 4];
            float af[8] = {a0.x, a0.y, a0.z, a0.w, a1.x, a1.y, a1.z, a1.w};
            float bf[8] = {b0.x, b0.y, b0.z, b0.w, b1.x, b1.y, b1.z, b1.w};
#pragma unroll
            for (int i = 0; i < 8; i++)
#pragma unroll
                for (int j = 0; j < 8; j++) acc[i][j] += af[i] * bf[j];
        }
        __syncthreads();
    }

#pragma unroll
    for (int i = 0; i < 8; i++) {
        long r2 = brow + ty * 8 + i;
        long co = (r2 & 63) * ocb + (r2 >> 6) * oct + bcol;
#pragma unroll
        for (int j = 0; j < 8; j++)
            C[co + tx * 8 + j] = acc[i][j] + bias[bcol + tx * 8 + j];
    }
}

// ---------------- persistent recurrence with tf32 mma.sync ----------------
// 128 blocks x 256 threads (8 warps). Block owns permuted cols [bid*32, bid*32+32).
// Warp decomposition: kh = wid>>2 (split-K half), wn = (wid>>1)&1 (16-col group), wm = wid&1 (32-row group).
// W slice (32 cols x 1024 k, tf32) preloaded to smem once. Per step: stage h chunks (Kc=32, x2 halves,
// double-buffered), mma, partial sums to Zs[2], pointwise, grid barrier.
__global__ __launch_bounds__(256) void lstm_layer_persist(int layer, int ep_base)
{
    extern __shared__ float dyn[];
    float* W_s = dyn;                  // 32*1024 floats, [n][k ^ ((n&7)<<2)]
    float* As_ = dyn + 32 * 1024;      // [buf2][half2][64][32] = 8192 floats
    float* Zs  = As_ + 8192;           // [half2][64][40] = 5120 floats

    const float* Wh = (layer == 0) ? (g_W0p + (size_t)VV * G4)
                                   : (g_W1p + (size_t)MEM * G4);
    float* c_st = g_c[layer];
    const int bid = blockIdx.x;
    const int tid = threadIdx.x;
    const int n0 = bid * 32;

    const int wid = tid >> 5, lane = tid & 31;
    const int gid = lane >> 2, tig = lane & 3;
    const int kh = wid >> 2;
    const int wn = (wid >> 1) & 1;
    const int wm = wid & 1;

    // preload W slice into smem (tf32 already)
    for (int idx = tid; idx < 32 * 1024; idx += 256) {
        int k = idx >> 5, n = idx & 31;
        W_s[n * 1024 + (k ^ ((n & 7) << 2))] = Wh[(size_t)k * G4 + n0 + n];
    }
    __syncthreads();

    // staging maps: f = tid + i*256, i<4: half = f>>9, row = (f>>3)&63, k4 = f&7
    int s_half[4], s_row[4], s_sw[4], s_off[4];
#pragma unroll
    for (int i = 0; i < 4; i++) {
        int f = tid + i * 256;
        s_half[i] = f >> 9;
        s_row[i] = (f >> 3) & 63;
        int k4 = f & 7;
        s_sw[i] = s_half[i] * 2048 + s_row[i] * 32 + ((k4 * 4) ^ ((s_row[i] & 7) * 4));
        s_off[i] = s_row[i] * 1024 + s_half[i] * 512 + k4 * 4;
    }

    const int arow0 = wm * 32 + gid;          // + mt*16 (+8)
    const int nfr0 = wn * 16 + gid;           // + nt*8
    const int asb = kh * 2048;                // half base inside As buffer

    for (int t = 0; t < TT; t++) {
        const float* hr = g_h2[layer][t & 1];
        float* hw = g_h2[layer][(t + 1) & 1];

        float acc[2][2][4];
#pragma unroll
        for (int mt = 0; mt < 2; mt++)
#pragma unroll
            for (int nt = 0; nt < 2; nt++)
#pragma unroll
                for (int q = 0; q < 4; q++) acc[mt][nt][q] = 0.0f;

        // stage chunk 0 into buf 0
        {
            float4 v[4];
#pragma unroll
            for (int i = 0; i < 4; i++) v[i] = __ldcg((const float4*)(hr + s_off[i]));
#pragma unroll
            for (int i = 0; i < 4; i++) {
                v[i].x = to_tf32(v[i].x); v[i].y = to_tf32(v[i].y);
                v[i].z = to_tf32(v[i].z); v[i].w = to_tf32(v[i].w);
                *(float4*)&As_[s_sw[i]] = v[i];
            }
        }

        for (int kc = 0; kc < 16; kc++) {
            __syncthreads();
            float4 pf[4];
            if (kc < 15) {
#pragma unroll
                for (int i = 0; i < 4; i++)
                    pf[i] = __ldcg((const float4*)(hr + s_off[i] + (kc + 1) * 32));
            }
            const float* Ab = As_ + (kc & 1) * 4096 + asb;
            const int kgb = kh * 512 + kc * 32;
#pragma unroll
            for (int kk = 0; kk < 4; kk++) {
                int kx0 = (kk * 8 + tig) ^ (gid * 4);
                int kx1 = (kk * 8 + tig + 4) ^ (gid * 4);
                uint32_t a[2][4];
#pragma unroll
                for (int mt = 0; mt < 2; mt++) {
                    int r0 = arow0 + mt * 16;
                    a[mt][0] = fu(Ab[r0 * 32 + kx0]);
                    a[mt][1] = fu(Ab[(r0 + 8) * 32 + kx0]);
                    a[mt][2] = fu(Ab[r0 * 32 + kx1]);
                    a[mt][3] = fu(Ab[(r0 + 8) * 32 + kx1]);
                }
                int kg0 = kgb + kk * 8 + tig;
#pragma unroll
                for (int nt = 0; nt < 2; nt++) {
                    int n = nfr0 + nt * 8;
                    uint32_t b0 = fu(W_s[n * 1024 + (kg0 ^ (gid * 4))]);
                    uint32_t b1 = fu(W_s[n * 1024 + ((kg0 + 4) ^ (gid * 4))]);
#pragma unroll
                    for (int mt = 0; mt < 2; mt++)
                        mma8(acc[mt][nt], a[mt][0], a[mt][1], a[mt][2], a[mt][3], b0, b1);
                }
            }
            if (kc < 15) {
                int nb = ((kc & 1) ^ 1) * 4096;
#pragma unroll
                for (int i = 0; i < 4; i++) {
                    pf[i].x = to_tf32(pf[i].x); pf[i].y = to_tf32(pf[i].y);
                    pf[i].z = to_tf32(pf[i].z); pf[i].w = to_tf32(pf[i].w);
                    *(float4*)&As_[nb + s_sw[i]] = pf[i];
                }
            }
        }

        // write split-K partials to Zs[kh]
#pragma unroll
        for (int mt = 0; mt < 2; mt++) {
            int row = wm * 32 + mt * 16 + gid;
#pragma unroll
            for (int nt = 0; nt < 2; nt++) {
                int col = wn * 16 + nt * 8 + tig * 2;
                *(float2*)&Zs[kh * 2560 + row * 40 + col] =
                    make_float2(acc[mt][nt][0], acc[mt][nt][1]);
                *(float2*)&Zs[kh * 2560 + (row + 8) * 40 + col] =
                    make_float2(acc[mt][nt][2], acc[mt][nt][3]);
            }
        }
        __syncthreads();

        // pointwise: 512 elems (64 batch x 8 units), 2 per thread
#pragma unroll
        for (int e = tid; e < 512; e += 256) {
            int m = e >> 3, j = e & 7;
            float4 zx = *(const float4*)(g_Zx + (size_t)t * BB * G4 + (size_t)m * G4 + n0 + j * 4);
            float4 z0 = *(const float4*)&Zs[m * 40 + j * 4];
            float4 z1 = *(const float4*)&Zs[2560 + m * 40 + j * 4];
            float zi = zx.x + z0.x + z1.x;
            float zj = zx.y + z0.y + z1.y;
            float zf = zx.z + z0.z + z1.z;
            float zo = zx.w + z0.w + z1.w;
            int ci = m * MEM + bid * 8 + j;
            float c = c_st[ci];
            float cn = c * sigm(zf + 1.0f) + sigm(zi) * tanhf(zj);
            float hn = tanhf(cn) * sigm(zo);
            c_st[ci] = cn;
            hw[ci] = hn;
            g_hall[(size_t)t * BB * MEM + ci] = hn;
        }

        // grid barrier
        __syncthreads();
        int want = ep_base + t + 1;
        if (tid == 0) {
            __threadfence();
            g_arrive[bid] = want;
        }
        if (tid < 128) {
            while (g_arrive[tid] < want) { }
        }
        __syncthreads();
        __threadfence();
    }
}

// ---------------- pack final_state [2, B, 2*MEM] ----------------
__global__ void state_pack(float* __restrict__ out)
{
    int i = blockIdx.x * 256 + threadIdx.x;
    int l = i / (BB * 2 * MEM);
    int rem = i % (BB * 2 * MEM);
    int b = rem / (2 * MEM);
    int u = rem % (2 * MEM);
    out[i] = (u < MEM) ? g_c[l][b * MEM + u] : g_h2[l][0][b * MEM + (u - MEM)];
}

extern "C" void kernel_launch(void* const* d_in, const int* in_sizes, int n_in,
                              void* d_out, int out_size)
{
    const float* x    = (const float*)d_in[0];
    const float* s0   = (const float*)d_in[1];
    const float* s1   = (const float*)d_in[2];
    const float* W0   = (const float*)d_in[3];
    const float* b0   = (const float*)d_in[4];
    const float* W1   = (const float*)d_in[5];
    const float* b1   = (const float*)d_in[6];
    const float* Wout = (const float*)d_in[7];
    const float* bout = (const float*)d_in[8];
    float* out = (float*)d_out;

    const int LSTM_SMEM = (32 * 1024 + 8192 + 5120) * 4;   // 184320 B
    static int attr_done = 0;
    cudaFuncSetAttribute(lstm_layer_persist,
                         cudaFuncAttributeMaxDynamicSharedMemorySize, LSTM_SMEM);
    (void)attr_done;

    init_state<<<256, 256>>>(s0, s1);

    {
        size_t total = (size_t)(VV + MEM) * G4 + (size_t)(2 * MEM) * G4;
        int blocks = (int)((total + 255) / 256);
        permute_w<<<blocks, 256>>>(W0, b0, W1, b1);
    }
    transpose_w2<<<dim3((VV + MEM) / 32, G4 / 32), 256>>>(W0, 0);
    transpose_w2<<<dim3((2 * MEM) / 32, G4 / 32), 256>>>(W1, 1);

    // Phase 1 (tf32 mma): Zx = x @ W0[:256,:] + b0   (M=32768, N=4096, K=256)
    gemm_mma<<<dim3(64, 256), 256>>>(x, (long)TT * VV, (long)VV,
                                     (long)(VV + MEM), VV, 0, 0);

    // Layer 0 recurrence
    lstm_layer_persist<<<128, 256, LSTM_SMEM>>>(0, 0);

    // Phase 3 (tf32 mma): Zx = h0_all @ W1[:1024,:] + b1   (M=32768, N=4096, K=1024)
    gemm_mma<<<dim3(64, 256), 256>>>(nullptr, (long)MEM, (long)BB * MEM,
                                     (long)(2 * MEM), MEM, 1, 1);

    // Layer 1 recurrence
    lstm_layer_persist<<<128, 256, LSTM_SMEM>>>(1, TT);

    // Phase 5 (scalar fp32): out = h1_all @ W_out + b_out
    dim3 g5(VV / 128, (TT * BB) / 128);
    gemm_big<<<g5, 256>>>((long)MEM, (long)BB * MEM,
                          Wout, bout, out,
                          (long)TT * VV, (long)VV, VV, MEM);

    state_pack<<<1024, 256>>>(out + (size_t)BB * TT * VV);
}

// round 5
// speedup vs baseline: 2.5319x; 1.1239x over previous
#include <cuda_runtime.h>
#include <math.h>
#include <stdint.h>

#define BB 64
#define TT 512
#define VV 256
#define MEM 1024
#define G4 4096

// ---------------- device scratch ----------------
__device__ float g_Zx[(size_t)TT * BB * G4];          // input-side z (+bias), gate-permuted cols
__device__ float g_hall[(size_t)TT * BB * MEM];       // per-layer h sequence fp32 (reused)
__device__ float g_c[2][BB * MEM];                    // cell state per layer
__device__ float g_h2[2][2][BB * MEM];                // h state, tf32-rounded, double-buffered
__device__ float g_hfin[2][BB * MEM];                 // final-step h, full fp32
__device__ float g_W0p[(VV + MEM) * G4];              // W0 gate-permuted cols, K-major, tf32
__device__ float g_W1p[(2 * MEM) * G4];               // W1 gate-permuted cols, K-major, tf32
__device__ float g_W0t[(size_t)G4 * (VV + MEM)];      // W0^T [n][k], tf32
__device__ float g_W1t[(size_t)G4 * (2 * MEM)];      // W1^T [n][k], tf32
__device__ float g_b0p[G4];
__device__ float g_b1p[G4];
__device__ volatile int g_arrive[128];

__device__ __forceinline__ float sigm(float x) { return 1.0f / (1.0f + expf(-x)); }
__device__ __forceinline__ float to_tf32(float x) {
    float r; asm("cvt.rna.tf32.f32 %0, %1;" : "=f"(r) : "f"(x)); return r;
}
__device__ __forceinline__ uint32_t fu(float x) { return __float_as_uint(x); }
__device__ __forceinline__ uint32_t smem_u32(const void* p) {
    uint32_t a;
    asm("{ .reg .u64 t; cvta.to.shared.u64 t, %1; cvt.u32.u64 %0, t; }" : "=r"(a) : "l"(p));
    return a;
}
__device__ __forceinline__ void cpa16(uint32_t dst, const void* src) {
    asm volatile("cp.async.cg.shared.global [%0], [%1], 16;" :: "r"(dst), "l"(src));
}
__device__ __forceinline__ void cpa_commit() { asm volatile("cp.async.commit_group;" ::: "memory"); }

__device__ __forceinline__ void mma8(float* d, uint32_t a0, uint32_t a1, uint32_t a2, uint32_t a3,
                                     uint32_t b0, uint32_t b1) {
    asm volatile("mma.sync.aligned.m16n8k8.row.col.f32.tf32.tf32.f32 "
                 "{%0,%1,%2,%3}, {%4,%5,%6,%7}, {%8,%9}, {%0,%1,%2,%3};"
                 : "+f"(d[0]), "+f"(d[1]), "+f"(d[2]), "+f"(d[3])
                 : "r"(a0), "r"(a1), "r"(a2), "r"(a3), "r"(b0), "r"(b1));
}

// ---------------- init ----------------
__global__ void init_state(const float* __restrict__ s0, const float* __restrict__ s1) {
    int i = blockIdx.x * 256 + threadIdx.x;
    int b = i / MEM, u = i % MEM;
    g_c[0][i] = s0[b * 2 * MEM + u];
    g_h2[0][0][i] = to_tf32(s0[b * 2 * MEM + MEM + u]);
    g_c[1][i] = s1[b * 2 * MEM + u];
    g_h2[1][0][i] = to_tf32(s1[b * 2 * MEM + MEM + u]);
    if (blockIdx.x == 0 && threadIdx.x < 128) g_arrive[threadIdx.x] = 0;
}

// ---------------- gate-permuted K-major tf32 weights + biases ----------------
__global__ void permute_w(const float* __restrict__ W0, const float* __restrict__ b0,
                          const float* __restrict__ W1, const float* __restrict__ b1) {
    size_t i = (size_t)blockIdx.x * 256 + threadIdx.x;
    const size_t n0 = (size_t)(VV + MEM) * G4;
    const size_t n1 = (size_t)(2 * MEM) * G4;
    if (i < n0) {
        int c = (int)(i & 4095); size_t r = i >> 12;
        g_W0p[i] = to_tf32(W0[r * G4 + (size_t)((c & 3) * 1024 + (c >> 2))]);
    } else if (i < n0 + n1) {
        size_t k = i - n0;
        int c = (int)(k & 4095); size_t r = k >> 12;
        g_W1p[k] = to_tf32(W1[r * G4 + (size_t)((c & 3) * 1024 + (c >> 2))]);
    }
    if (i < G4) {
        int c = (int)i;
        g_b0p[c] = b0[(c & 3) * 1024 + (c >> 2)];
        g_b1p[c] = b1[(c & 3) * 1024 + (c >> 2)];
    }
}

// ---------------- transposed tf32 weights WT[n][k] ----------------
__global__ __launch_bounds__(256) void transpose_w2(const float* __restrict__ W, int sel) {
    __shared__ float s[32][33];
    int tx = threadIdx.x & 31, ty = threadIdx.x >> 5;
    int k0 = blockIdx.x * 32, c0 = blockIdx.y * 32;
    float* dst = (sel == 0) ? g_W0t : g_W1t;
    long wst = (sel == 0) ? (VV + MEM) : (2 * MEM);
#pragma unroll
    for (int j = 0; j < 4; j++)
        s[ty + j * 8][tx] = W[(size_t)(k0 + ty + j * 8) * G4 + c0 + tx];
    __syncthreads();
#pragma unroll
    for (int j = 0; j < 4; j++) {
        int c = c0 + ty + j * 8;
        int n = (c & 1023) * 4 + (c >> 10);
        dst[(size_t)n * wst + k0 + tx] = to_tf32(s[tx][ty + j * 8]);
    }
}

// ---------------- phase GEMM (tf32 mma.sync), unchanged from round 4 ----------------
__global__ __launch_bounds__(256) void gemm_mma(
    const float* __restrict__ Ain, long sb, long st,
    long wstride, int K, int src_gh, int w_sel)
{
    const float* A = src_gh ? (const float*)g_hall : Ain;
    const float* WT = (w_sel == 0) ? g_W0t : g_W1t;
    const float* bias = (w_sel == 0) ? g_b0p : g_b1p;
    float* C = (float*)g_Zx;

    __shared__ float As[128 * 32];
    __shared__ float Bs[64 * 32];

    const int tid = threadIdx.x;
    const int wid = tid >> 5, lane = tid & 31;
    const int gid = lane >> 2, tig = lane & 3;
    const int wm = wid & 3, wn = wid >> 2;
    const long brow = (long)blockIdx.y * 128;
    const int bcol = blockIdx.x * 64;

    int a_sw[4];
    const float* a_ptr[4];
#pragma unroll
    for (int i = 0; i < 4; i++) {
        int f = tid + i * 256;
        int row = f >> 3, k4 = f & 7;
        a_sw[i] = row * 32 + ((k4 * 4) ^ ((row & 7) * 4));
        long r = brow + row;
        a_ptr[i] = A + (r & 63) * sb + (r >> 6) * st + k4 * 4;
    }
    int b_sw[2];
    const float* b_ptr[2];
#pragma unroll
    for (int i = 0; i < 2; i++) {
        int f = tid + i * 256;
        int n = f >> 3, k4 = f & 7;
        b_sw[i] = n * 32 + ((k4 * 4) ^ ((n & 7) * 4));
        b_ptr[i] = WT + (size_t)(bcol + n) * wstride + k4 * 4;
    }

    float acc[2][4][4];
#pragma unroll
    for (int mt = 0; mt < 2; mt++)
#pragma unroll
        for (int nt = 0; nt < 4; nt++)
#pragma unroll
            for (int q = 0; q < 4; q++) acc[mt][nt][q] = 0.0f;

    const int arow0 = wm * 32 + gid;
    const int nb0 = wn * 32 + gid;

    for (int kb = 0; kb < K; kb += 32) {
        float4 av[4], bv[2];
#pragma unroll
        for (int i = 0; i < 4; i++) av[i] = *(const float4*)(a_ptr[i] + kb);
#pragma unroll
        for (int i = 0; i < 2; i++) bv[i] = *(const float4*)(b_ptr[i] + kb);
        __syncthreads();
#pragma unroll
        for (int i = 0; i < 4; i++) {
            float4 v = av[i];
            v.x = to_tf32(v.x); v.y = to_tf32(v.y); v.z = to_tf32(v.z); v.w = to_tf32(v.w);
            *(float4*)&As[a_sw[i]] = v;
        }
#pragma unroll
        for (int i = 0; i < 2; i++) *(float4*)&Bs[b_sw[i]] = bv[i];
        __syncthreads();

#pragma unroll
        for (int kk = 0; kk < 4; kk++) {
            int kx0 = (kk * 8 + tig) ^ (gid * 4);
            int kx1 = (kk * 8 + tig + 4) ^ (gid * 4);
            uint32_t a[2][4];
#pragma unroll
            for (int mt = 0; mt < 2; mt++) {
                int r0 = arow0 + mt * 16;
                a[mt][0] = fu(As[r0 * 32 + kx0]);
                a[mt][1] = fu(As[(r0 + 8) * 32 + kx0]);
                a[mt][2] = fu(As[r0 * 32 + kx1]);
                a[mt][3] = fu(As[(r0 + 8) * 32 + kx1]);
            }
#pragma unroll
            for (int nt = 0; nt < 4; nt++) {
                int n = nb0 + nt * 8;
                uint32_t b0 = fu(Bs[n * 32 + kx0]);
                uint32_t b1 = fu(Bs[n * 32 + kx1]);
#pragma unroll
                for (int mt = 0; mt < 2; mt++)
                    mma8(acc[mt][nt], a[mt][0], a[mt][1], a[mt][2], a[mt][3], b0, b1);
            }
        }
        __syncthreads();
    }

#pragma unroll
    for (int mt = 0; mt < 2; mt++) {
        long r2 = brow + wm * 32 + mt * 16 + gid;
#pragma unroll
        for (int nt = 0; nt < 4; nt++) {
            int col = bcol + wn * 32 + nt * 8 + tig * 2;
            float bz0 = bias[col], bz1 = bias[col + 1];
            float2 v0 = { acc[mt][nt][0] + bz0, acc[mt][nt][1] + bz1 };
            float2 v1 = { acc[mt][nt][2] + bz0, acc[mt][nt][3] + bz1 };
            *(float2*)(C + (size_t)r2 * G4 + col) = v0;
            *(float2*)(C + (size_t)(r2 + 8) * G4 + col) = v1;
        }
    }
}

// ---------------- scalar fp32 GEMM (phase 5) ----------------
__global__ __launch_bounds__(256) void gemm_big(
    long sb, long st,
    const float* __restrict__ W, const float* __restrict__ bias,
    float* __restrict__ C, long ocb, long oct,
    int N, int K)
{
    const float* A = (const float*)g_hall;
    __shared__ float As[8][128];
    __shared__ float Bs[8][128];

    int tid = threadIdx.x;
    int brow = blockIdx.y * 128;
    int bcol = blockIdx.x * 128;
    int ty = tid >> 4;
    int tx = tid & 15;
    int arow = tid >> 1;
    int ak = (tid & 1) * 4;
    int bk = tid >> 5;
    int bn = (tid & 31) * 4;

    long r = brow + arow;
    const float* Arow = A + (r & 63) * sb + (r >> 6) * st;
    const float* Wp0 = W + (long)bk * N + bcol + bn;

    float acc[8][8];
#pragma unroll
    for (int i = 0; i < 8; i++)
#pragma unroll
        for (int j = 0; j < 8; j++) acc[i][j] = 0.0f;

    for (int k0 = 0; k0 < K; k0 += 8) {
        float4 av = *(const float4*)(Arow + k0 + ak);
        As[ak + 0][arow] = av.x;
        As[ak + 1][arow] = av.y;
        As[ak + 2][arow] = av.z;
        As[ak + 3][arow] = av.w;
        *(float4*)&Bs[bk][bn] = *(const float4*)(Wp0 + (long)k0 * N);
        __syncthreads();
#pragma unroll
        for (int k = 0; k < 8; k++) {
            float4 a0 = *(const float4*)&As[k][ty * 8];
            float4 a1 = *(const float4*)&As[k][ty * 8 + 4];
            float4 b0 = *(const float4*)&Bs[k][tx * 8];
            float4 b1 = *(const float4*)&Bs[k][tx * 8 + 4];
            float af[8] = {a0.x, a0.y, a0.z, a0.w, a1.x, a1.y, a1.z, a1.w};
            float bf[8] = {b0.x, b0.y, b0.z, b0.w, b1.x, b1.y, b1.z, b1.w};
#pragma unroll
            for (int i = 0; i < 8; i++)
#pragma unroll
                for (int j = 0; j < 8; j++) acc[i][j] += af[i] * bf[j];
        }
        __syncthreads();
    }

#pragma unroll
    for (int i = 0; i < 8; i++) {
        long r2 = brow + ty * 8 + i;
        long co = (r2 & 63) * ocb + (r2 >> 6) * oct + bcol;
#pragma unroll
        for (int j = 0; j < 8; j++)
            C[co + tx * 8 + j] = acc[i][j] + bias[bcol + tx * 8 + j];
    }
}

// ---------------- persistent recurrence: cp.async pipeline + 2m x 4kq warps ----------------
// smem floats: W_s[0,32768) | As 3x4096 [32768,45056) | Zs 4x64x36 [45056,54272) | Zx 2048 [54272,56320)
#define SM_W 0
#define SM_AS 32768
#define SM_ZS 45056
#define SM_ZX 54272
#define SM_TOTAL_F 56320

__global__ __launch_bounds__(256) void lstm_layer_persist(int layer, int ep_base)
{
    extern __shared__ float dyn[];
    float* W_s = dyn + SM_W;
    float* As_ = dyn + SM_AS;
    float* Zs  = dyn + SM_ZS;
    float* Zx_s = dyn + SM_ZX;

    const float* Wh = (layer == 0) ? (g_W0p + (size_t)VV * G4)
                                   : (g_W1p + (size_t)MEM * G4);
    float* c_st = g_c[layer];
    const int bid = blockIdx.x;
    const int tid = threadIdx.x;
    const int n0 = bid * 32;

    const int wid = tid >> 5, lane = tid & 31;
    const int gid = lane >> 2, tig = lane & 3;
    const int kq = wid & 3;           // k quarter (256 k)
    const int wm = wid >> 2;          // m half (32 rows)

    // preload W slice [32 cols][1024 k], swizzled
    for (int idx = tid; idx < 32 * 1024; idx += 256) {
        int k = idx >> 5, n = idx & 31;
        W_s[n * 1024 + (k ^ ((n & 7) * 4))] = Wh[(size_t)k * G4 + n0 + n];
    }

    const uint32_t sbase = smem_u32(dyn);

    // h-chunk staging maps: granule g = tid + i*256: q=g>>8, row=(g>>2)&63, k4=g&3
    uint32_t a_dst[4]; int a_soff[4];
#pragma unroll
    for (int i = 0; i < 4; i++) {
        int g = tid + i * 256;
        int q = g >> 8, row = (g >> 2) & 63, k4 = g & 3;
        a_dst[i] = sbase + (uint32_t)(SM_AS + q * 1024 + row * 16 + ((k4 * 4) ^ (((row >> 1) & 3) * 4))) * 4u;
        a_soff[i] = row * 1024 + q * 256 + k4 * 4;
    }
    // Zx staging maps: g = tid + i*256: m=g>>3, c4=g&7
    uint32_t zx_dst[2]; int zx_soff[2];
#pragma unroll
    for (int i = 0; i < 2; i++) {
        int g = tid + i * 256;
        int m = g >> 3, c4 = g & 7;
        zx_dst[i] = sbase + (uint32_t)(SM_ZX + m * 32 + c4 * 4) * 4u;
        zx_soff[i] = m * G4 + n0 + c4 * 4;
    }

    // fragment constants
    const int fA = (gid >> 1) * 4;
    int a_base[2];
#pragma unroll
    for (int mt = 0; mt < 2; mt++)
        a_base[mt] = kq * 1024 + (wm * 32 + mt * 16 + gid) * 16;
    int b_nidx[4];
#pragma unroll
    for (int nt = 0; nt < 4; nt++)
        b_nidx[nt] = (nt * 8 + gid) * 1024;
    const int swzB = gid * 4;

    // pointwise constants + c registers
    const int pm0 = tid >> 3, pj = tid & 7;
    const int ci0 = pm0 * MEM + bid * 8 + pj;
    const int ci1 = (pm0 + 32) * MEM + bid * 8 + pj;
    float creg0 = c_st[ci0], creg1 = c_st[ci1];

    __syncthreads();

    for (int t = 0; t < TT; t++) {
        const float* hr = g_h2[layer][t & 1];
        float* hw = g_h2[layer][(t + 1) & 1];
        const float* zxp = g_Zx + (size_t)t * BB * G4;

        // group 0: chunk 0 + Zx ; group 1: chunk 1
#pragma unroll
        for (int i = 0; i < 4; i++) cpa16(a_dst[i], hr + a_soff[i]);
#pragma unroll
        for (int i = 0; i < 2; i++) cpa16(zx_dst[i], zxp + zx_soff[i]);
        cpa_commit();
#pragma unroll
        for (int i = 0; i < 4; i++) cpa16(a_dst[i] + 16384u, hr + a_soff[i] + 16);
        cpa_commit();

        float acc[2][4][4];
#pragma unroll
        for (int mt = 0; mt < 2; mt++)
#pragma unroll
            for (int nt = 0; nt < 4; nt++)
#pragma unroll
                for (int q = 0; q < 4; q++) acc[mt][nt][q] = 0.0f;

        for (int kc = 0; kc < 16; kc++) {
            if (kc < 15) asm volatile("cp.async.wait_group 1;" ::: "memory");
            else         asm volatile("cp.async.wait_group 0;" ::: "memory");
            __syncthreads();
            if (kc < 14) {
                uint32_t boff = (uint32_t)((kc + 2) % 3) * 16384u;
                const float* src0 = hr + (kc + 2) * 16;
#pragma unroll
                for (int i = 0; i < 4; i++) cpa16(a_dst[i] + boff, src0 + a_soff[i]);
                cpa_commit();
            }
            const float* Ab = As_ + (kc % 3) * 4096;
#pragma unroll
            for (int kk = 0; kk < 2; kk++) {
                int kl0 = (kk * 8 + tig) ^ fA;
                int kl1 = (kk * 8 + tig + 4) ^ fA;
                uint32_t a[2][4];
#pragma unroll
                for (int mt = 0; mt < 2; mt++) {
                    a[mt][0] = fu(Ab[a_base[mt] + kl0]);
                    a[mt][1] = fu(Ab[a_base[mt] + 128 + kl0]);
                    a[mt][2] = fu(Ab[a_base[mt] + kl1]);
                    a[mt][3] = fu(Ab[a_base[mt] + 128 + kl1]);
                }
                int kg = kq * 256 + kc * 16 + kk * 8 + tig;
#pragma unroll
                for (int nt = 0; nt < 4; nt++) {
                    uint32_t b0 = fu(W_s[b_nidx[nt] + (kg ^ swzB)]);
                    uint32_t b1 = fu(W_s[b_nidx[nt] + ((kg + 4) ^ swzB)]);
#pragma unroll
                    for (int mt = 0; mt < 2; mt++)
                        mma8(acc[mt][nt], a[mt][0], a[mt][1], a[mt][2], a[mt][3], b0, b1);
                }
            }
        }

        // store split-K partials
#pragma unroll
        for (int mt = 0; mt < 2; mt++) {
            int row = wm * 32 + mt * 16 + gid;
#pragma unroll
            for (int nt = 0; nt < 4; nt++) {
                int col = nt * 8 + tig * 2;
                *(float2*)&Zs[kq * 2304 + row * 36 + col] =
                    make_float2(acc[mt][nt][0], acc[mt][nt][1]);
                *(float2*)&Zs[kq * 2304 + (row + 8) * 36 + col] =
                    make_float2(acc[mt][nt][2], acc[mt][nt][3]);
            }
        }
        __syncthreads();

        // pointwise: 2 elems/thread (m = pm0 and pm0+32, unit j = pj)
#pragma unroll
        for (int e = 0; e < 2; e++) {
            int m = pm0 + e * 32;
            int ci = e ? ci1 : ci0;
            float4 z = *(const float4*)&Zx_s[m * 32 + pj * 4];
#pragma unroll
            for (int q = 0; q < 4; q++) {
                float4 p = *(const float4*)&Zs[q * 2304 + m * 36 + pj * 4];
                z.x += p.x; z.y += p.y; z.z += p.z; z.w += p.w;
            }
            float c = e ? creg1 : creg0;
            float cn = c * sigm(z.z + 1.0f) + sigm(z.x) * tanhf(z.y);
            float hn = tanhf(cn) * sigm(z.w);
            if (e) creg1 = cn; else creg0 = cn;
            hw[ci] = to_tf32(hn);
            g_hall[(size_t)t * BB * MEM + ci] = hn;
            if (t == TT - 1) g_hfin[layer][ci] = hn;
        }

        // grid barrier
        __syncthreads();
        int want = ep_base + t + 1;
        if (tid == 0) {
            __threadfence();
            g_arrive[bid] = want;
        }
        if (tid < 128) {
            while (g_arrive[tid] < want) { }
        }
        __syncthreads();
        __threadfence();
    }

    c_st[ci0] = creg0;
    c_st[ci1] = creg1;
}

// ---------------- pack final_state [2, B, 2*MEM] ----------------
__global__ void state_pack(float* __restrict__ out)
{
    int i = blockIdx.x * 256 + threadIdx.x;
    int l = i / (BB * 2 * MEM);
    int rem = i % (BB * 2 * MEM);
    int b = rem / (2 * MEM);
    int u = rem % (2 * MEM);
    out[i] = (u < MEM) ? g_c[l][b * MEM + u] : g_hfin[l][b * MEM + (u - MEM)];
}

extern "C" void kernel_launch(void* const* d_in, const int* in_sizes, int n_in,
                              void* d_out, int out_size)
{
    const float* x    = (const float*)d_in[0];
    const float* s0   = (const float*)d_in[1];
    const float* s1   = (const float*)d_in[2];
    const float* W0   = (const float*)d_in[3];
    const float* b0   = (const float*)d_in[4];
    const float* W1   = (const float*)d_in[5];
    const float* b1   = (const float*)d_in[6];
    const float* Wout = (const float*)d_in[7];
    const float* bout = (const float*)d_in[8];
    float* out = (float*)d_out;

    const int LSTM_SMEM = SM_TOTAL_F * 4;   // 225280 B
    cudaFuncSetAttribute(lstm_layer_persist,
                         cudaFuncAttributeMaxDynamicSharedMemorySize, LSTM_SMEM);

    init_state<<<256, 256>>>(s0, s1);

    {
        size_t total = (size_t)(VV + MEM) * G4 + (size_t)(2 * MEM) * G4;
        int blocks = (int)((total + 255) / 256);
        permute_w<<<blocks, 256>>>(W0, b0, W1, b1);
    }
    transpose_w2<<<dim3((VV + MEM) / 32, G4 / 32), 256>>>(W0, 0);
    transpose_w2<<<dim3((2 * MEM) / 32, G4 / 32), 256>>>(W1, 1);

    // Phase 1: Zx = x @ W0[:256,:] + b0
    gemm_mma<<<dim3(64, 256), 256>>>(x, (long)TT * VV, (long)VV,
                                     (long)(VV + MEM), VV, 0, 0);

    // Layer 0 recurrence
    lstm_layer_persist<<<128, 256, LSTM_SMEM>>>(0, 0);

    // Phase 3: Zx = h0_all @ W1[:1024,:] + b1
    gemm_mma<<<dim3(64, 256), 256>>>(nullptr, (long)MEM, (long)BB * MEM,
                                     (long)(2 * MEM), MEM, 1, 1);

    // Layer 1 recurrence
    lstm_layer_persist<<<128, 256, LSTM_SMEM>>>(1, TT);

    // Phase 5: out = h1_all @ W_out + b_out (fp32)
    dim3 g5(VV / 128, (TT * BB) / 128);
    gemm_big<<<g5, 256>>>((long)MEM, (long)BB * MEM,
                          Wout, bout, out,
                          (long)TT * VV, (long)VV, VV, MEM);

    state_pack<<<1024, 256>>>(out + (size_t)BB * TT * VV);
}

// round 8
// speedup vs baseline: 2.6735x; 1.0559x over previous
#include <cuda_runtime.h>
#include <math.h>
#include <stdint.h>

#define BB 64
#define TT 512
#define VV 256
#define MEM 1024
#define G4 4096

// ---------------- device scratch ----------------
__device__ float g_Zx[(size_t)TT * BB * G4];          // input-side z (+bias), gate-permuted cols
__device__ float g_hall[(size_t)TT * BB * MEM];       // per-layer h sequence fp32 (reused)
__device__ float g_c[2][BB * MEM];                    // cell state per layer
__device__ float g_h2[2][2][BB * MEM];                // h state, tf32-rounded, double-buffered
__device__ float g_hfin[2][BB * MEM];                 // final-step h, full fp32
__device__ float g_W0p[(VV + MEM) * G4];              // W0 gate-permuted cols, K-major, tf32
__device__ float g_W1p[(2 * MEM) * G4];               // W1 gate-permuted cols, K-major, tf32
__device__ float g_W0t[(size_t)G4 * (VV + MEM)];      // W0^T [n][k], tf32
__device__ float g_W1t[(size_t)G4 * (2 * MEM)];       // W1^T [n][k], tf32
__device__ float g_Wot[(size_t)VV * MEM];             // W_out^T [n][k], tf32
__device__ float g_b0p[G4];
__device__ float g_b1p[G4];
__device__ volatile int g_arrive[128];

__device__ __forceinline__ float sigm(float x) { return 1.0f / (1.0f + expf(-x)); }
__device__ __forceinline__ float to_tf32(float x) {
    float r; asm("cvt.rna.tf32.f32 %0, %1;" : "=f"(r) : "f"(x)); return r;
}
__device__ __forceinline__ uint32_t fu(float x) { return __float_as_uint(x); }
__device__ __forceinline__ uint32_t smem_u32(const void* p) {
    uint32_t a;
    asm("{ .reg .u64 t; cvta.to.shared.u64 t, %1; cvt.u32.u64 %0, t; }" : "=r"(a) : "l"(p));
    return a;
}
__device__ __forceinline__ void cpa16(uint32_t dst, const void* src) {
    asm volatile("cp.async.cg.shared.global [%0], [%1], 16;" :: "r"(dst), "l"(src));
}
__device__ __forceinline__ void cpa_commit() { asm volatile("cp.async.commit_group;" ::: "memory"); }
#define WAITG(n) asm volatile("cp.async.wait_group %0;" :: "n"(n) : "memory")

__device__ __forceinline__ void mma8(float* d, uint32_t a0, uint32_t a1, uint32_t a2, uint32_t a3,
                                     uint32_t b0, uint32_t b1) {
    asm volatile("mma.sync.aligned.m16n8k8.row.col.f32.tf32.tf32.f32 "
                 "{%0,%1,%2,%3}, {%4,%5,%6,%7}, {%8,%9}, {%0,%1,%2,%3};"
                 : "+f"(d[0]), "+f"(d[1]), "+f"(d[2]), "+f"(d[3])
                 : "r"(a0), "r"(a1), "r"(a2), "r"(a3), "r"(b0), "r"(b1));
}

// ---------------- init ----------------
__global__ void init_state(const float* __restrict__ s0, const float* __restrict__ s1) {
    int i = blockIdx.x * 256 + threadIdx.x;
    int b = i / MEM, u = i % MEM;
    g_c[0][i] = s0[b * 2 * MEM + u];
    g_h2[0][0][i] = to_tf32(s0[b * 2 * MEM + MEM + u]);
    g_c[1][i] = s1[b * 2 * MEM + u];
    g_h2[1][0][i] = to_tf32(s1[b * 2 * MEM + MEM + u]);
    if (blockIdx.x == 0 && threadIdx.x < 128) g_arrive[threadIdx.x] = 0;
}

// ---------------- gate-permuted K-major tf32 weights + biases (coalesced 4-gate gather) ----------------
__global__ void permute_w(const float* __restrict__ W0, const float* __restrict__ b0,
                          const float* __restrict__ W1, const float* __restrict__ b1) {
    size_t i = (size_t)blockIdx.x * 256 + threadIdx.x;
    const size_t n0 = (size_t)(VV + MEM) * MEM;       // (r,u) pairs for W0
    const size_t n1 = (size_t)(2 * MEM) * MEM;
    if (i < n0) {
        size_t r = i >> 10; int u = (int)(i & 1023);
        const float* src = W0 + r * G4 + u;
        float4 v;
        v.x = to_tf32(src[0]);
        v.y = to_tf32(src[1024]);
        v.z = to_tf32(src[2048]);
        v.w = to_tf32(src[3072]);
        *(float4*)&g_W0p[r * G4 + (size_t)u * 4] = v;
    } else if (i < n0 + n1) {
        size_t k = i - n0;
        size_t r = k >> 10; int u = (int)(k & 1023);
        const float* src = W1 + r * G4 + u;
        float4 v;
        v.x = to_tf32(src[0]);
        v.y = to_tf32(src[1024]);
        v.z = to_tf32(src[2048]);
        v.w = to_tf32(src[3072]);
        *(float4*)&g_W1p[r * G4 + (size_t)u * 4] = v;
    }
    if (i < MEM) {
        int u = (int)i;
        float4 vb0 = { b0[u], b0[1024 + u], b0[2048 + u], b0[3072 + u] };
        float4 vb1 = { b1[u], b1[1024 + u], b1[2048 + u], b1[3072 + u] };
        *(float4*)&g_b0p[u * 4] = vb0;
        *(float4*)&g_b1p[u * 4] = vb1;
    }
}

// ---------------- transposed tf32 weights WT[n][k] (gate-permuted n) ----------------
__global__ __launch_bounds__(256) void transpose_w2(const float* __restrict__ W, int sel) {
    __shared__ float s[32][33];
    int tx = threadIdx.x & 31, ty = threadIdx.x >> 5;
    int k0 = blockIdx.x * 32, c0 = blockIdx.y * 32;
    float* dst = (sel == 0) ? g_W0t : g_W1t;
    long wst = (sel == 0) ? (VV + MEM) : (2 * MEM);
#pragma unroll
    for (int j = 0; j < 4; j++)
        s[ty + j * 8][tx] = W[(size_t)(k0 + ty + j * 8) * G4 + c0 + tx];
    __syncthreads();
#pragma unroll
    for (int j = 0; j < 4; j++) {
        int c = c0 + ty + j * 8;
        int n = (c & 1023) * 4 + (c >> 10);
        dst[(size_t)n * wst + k0 + tx] = to_tf32(s[tx][ty + j * 8]);
    }
}

// ---------------- transposed tf32 W_out: g_Wot[n][k] ----------------
__global__ __launch_bounds__(256) void transpose_wout(const float* __restrict__ W) {
    __shared__ float s[32][33];
    int tx = threadIdx.x & 31, ty = threadIdx.x >> 5;
    int k0 = blockIdx.x * 32, c0 = blockIdx.y * 32;
#pragma unroll
    for (int j = 0; j < 4; j++)
        s[ty + j * 8][tx] = W[(size_t)(k0 + ty + j * 8) * VV + c0 + tx];
    __syncthreads();
#pragma unroll
    for (int j = 0; j < 4; j++) {
        int n = c0 + ty + j * 8;
        g_Wot[(size_t)n * MEM + k0 + tx] = to_tf32(s[tx][ty + j * 8]);
    }
}

// ---------------- tf32 mma GEMM: C[r, bcol..] = bias + A[r,:K] @ W[:K, bcol..] ----------------
// block 128x64, 8 warps (4m x 2n) of 32x32, Kc=32, XOR-swizzled smem.
// C addressing: co = (r&63)*ocb + (r>>6)*oct + col. w_sel: 0=g_W0t,1=g_W1t,2=g_Wot(out to Cout,bias_ext)
__global__ __launch_bounds__(256) void gemm_mma(
    const float* __restrict__ Ain, long sb, long st,
    long wstride, int K, int src_gh, int w_sel,
    float* __restrict__ Cout, const float* __restrict__ bias_ext,
    long ocb, long oct)
{
    const float* A = src_gh ? (const float*)g_hall : Ain;
    const float* WT = (w_sel == 0) ? g_W0t : ((w_sel == 1) ? g_W1t : g_Wot);
    const float* bias = (w_sel == 0) ? g_b0p : ((w_sel == 1) ? g_b1p : bias_ext);
    float* C = (w_sel == 2) ? Cout : (float*)g_Zx;

    __shared__ float As[128 * 32];
    __shared__ float Bs[64 * 32];

    const int tid = threadIdx.x;
    const int wid = tid >> 5, lane = tid & 31;
    const int gid = lane >> 2, tig = lane & 3;
    const int wm = wid & 3, wn = wid >> 2;
    const long brow = (long)blockIdx.y * 128;
    const int bcol = blockIdx.x * 64;

    int a_sw[4];
    const float* a_ptr[4];
#pragma unroll
    for (int i = 0; i < 4; i++) {
        int f = tid + i * 256;
        int row = f >> 3, k4 = f & 7;
        a_sw[i] = row * 32 + ((k4 * 4) ^ ((row & 7) * 4));
        long r = brow + row;
        a_ptr[i] = A + (r & 63) * sb + (r >> 6) * st + k4 * 4;
    }
    int b_sw[2];
    const float* b_ptr[2];
#pragma unroll
    for (int i = 0; i < 2; i++) {
        int f = tid + i * 256;
        int n = f >> 3, k4 = f & 7;
        b_sw[i] = n * 32 + ((k4 * 4) ^ ((n & 7) * 4));
        b_ptr[i] = WT + (size_t)(bcol + n) * wstride + k4 * 4;
    }

    float acc[2][4][4];
#pragma unroll
    for (int mt = 0; mt < 2; mt++)
#pragma unroll
        for (int nt = 0; nt < 4; nt++)
#pragma unroll
            for (int q = 0; q < 4; q++) acc[mt][nt][q] = 0.0f;

    const int arow0 = wm * 32 + gid;
    const int nb0 = wn * 32 + gid;

    for (int kb = 0; kb < K; kb += 32) {
        float4 av[4], bv[2];
#pragma unroll
        for (int i = 0; i < 4; i++) av[i] = *(const float4*)(a_ptr[i] + kb);
#pragma unroll
        for (int i = 0; i < 2; i++) bv[i] = *(const float4*)(b_ptr[i] + kb);
        __syncthreads();
#pragma unroll
        for (int i = 0; i < 4; i++) {
            float4 v = av[i];
            v.x = to_tf32(v.x); v.y = to_tf32(v.y); v.z = to_tf32(v.z); v.w = to_tf32(v.w);
            *(float4*)&As[a_sw[i]] = v;
        }
#pragma unroll
        for (int i = 0; i < 2; i++) *(float4*)&Bs[b_sw[i]] = bv[i];
        __syncthreads();

#pragma unroll
        for (int kk = 0; kk < 4; kk++) {
            int kx0 = (kk * 8 + tig) ^ (gid * 4);
            int kx1 = (kk * 8 + tig + 4) ^ (gid * 4);
            uint32_t a[2][4];
#pragma unroll
            for (int mt = 0; mt < 2; mt++) {
                int r0 = arow0 + mt * 16;
                a[mt][0] = fu(As[r0 * 32 + kx0]);
                a[mt][1] = fu(As[(r0 + 8) * 32 + kx0]);
                a[mt][2] = fu(As[r0 * 32 + kx1]);
                a[mt][3] = fu(As[(r0 + 8) * 32 + kx1]);
            }
#pragma unroll
            for (int nt = 0; nt < 4; nt++) {
                int n = nb0 + nt * 8;
                uint32_t b0 = fu(Bs[n * 32 + kx0]);
                uint32_t b1 = fu(Bs[n * 32 + kx1]);
#pragma unroll
                for (int mt = 0; mt < 2; mt++)
                    mma8(acc[mt][nt], a[mt][0], a[mt][1], a[mt][2], a[mt][3], b0, b1);
            }
        }
        __syncthreads();
    }

#pragma unroll
    for (int mt = 0; mt < 2; mt++) {
        long r2 = brow + wm * 32 + mt * 16 + gid;
        long co0 = (r2 & 63) * ocb + (r2 >> 6) * oct;
        long r3 = r2 + 8;
        long co1 = (r3 & 63) * ocb + (r3 >> 6) * oct;
#pragma unroll
        for (int nt = 0; nt < 4; nt++) {
            int col = bcol + wn * 32 + nt * 8 + tig * 2;
            float bz0 = bias[col], bz1 = bias[col + 1];
            float2 v0 = { acc[mt][nt][0] + bz0, acc[mt][nt][1] + bz1 };
            float2 v1 = { acc[mt][nt][2] + bz0, acc[mt][nt][3] + bz1 };
            *(float2*)(C + co0 + col) = v0;
            *(float2*)(C + co1 + col) = v1;
        }
    }
}

// ---------------- persistent recurrence ----------------
// smem floats: W_s [0,32768) | As 4x4096 [32768,49152) (Zs 9216 aliased at 32768) | Zx 2304 [49152,51456)
#define SM_AS 32768
#define SM_ZX 49152
#define SM_TOTAL_F 51456

__global__ __launch_bounds__(256) void lstm_layer_persist(int layer, int ep_base)
{
    extern __shared__ float dyn[];
    float* W_s = dyn;
    float* As_ = dyn + SM_AS;
    float* Zs  = dyn + SM_AS;          // aliased: used only after all chunks consumed
    float* Zx_s = dyn + SM_ZX;

    const float* Wh = (layer == 0) ? (g_W0p + (size_t)VV * G4)
                                   : (g_W1p + (size_t)MEM * G4);
    float* c_st = g_c[layer];
    const int bid = blockIdx.x;
    const int tid = threadIdx.x;
    const int n0 = bid * 32;

    const int wid = tid >> 5, lane = tid & 31;
    const int gid = lane >> 2, tig = lane & 3;
    const int kq = wid & 3;           // k quarter (256 k)
    const int wm = wid >> 2;          // m half (32 rows)

    // preload W slice [32 cols][1024 k], swizzled
    for (int idx = tid; idx < 32 * 1024; idx += 256) {
        int k = idx >> 5, n = idx & 31;
        W_s[n * 1024 + (k ^ ((n & 7) * 4))] = Wh[(size_t)k * G4 + n0 + n];
    }

    const uint32_t sbase = smem_u32(dyn);

    // h-chunk staging maps: granule g = tid + i*256: q=g>>8, row=(g>>2)&63, k4=g&3
    uint32_t a_dst[4]; int a_soff[4];
#pragma unroll
    for (int i = 0; i < 4; i++) {
        int g = tid + i * 256;
        int q = g >> 8, row = (g >> 2) & 63, k4 = g & 3;
        a_dst[i] = sbase + (uint32_t)(SM_AS + q * 1024 + row * 16 + ((k4 * 4) ^ (((row >> 1) & 3) * 4))) * 4u;
        a_soff[i] = row * 1024 + q * 256 + k4 * 4;
    }
    // Zx staging maps (stride 36): g = tid + i*256: m=g>>3, c4=g&7
    uint32_t zx_dst[2]; int zx_soff[2];
#pragma unroll
    for (int i = 0; i < 2; i++) {
        int g = tid + i * 256;
        int m = g >> 3, c4 = g & 7;
        zx_dst[i] = sbase + (uint32_t)(SM_ZX + m * 36 + c4 * 4) * 4u;
        zx_soff[i] = m * G4 + n0 + c4 * 4;
    }

    // fragment constants
    const int fA = (gid >> 1) * 4;
    int a_base[2];
#pragma unroll
    for (int mt = 0; mt < 2; mt++)
        a_base[mt] = kq * 1024 + (wm * 32 + mt * 16 + gid) * 16;
    int b_nidx[4];
#pragma unroll
    for (int nt = 0; nt < 4; nt++)
        b_nidx[nt] = (nt * 8 + gid) * 1024;
    const int swzB = gid * 4;

    // pointwise constants + c registers
    const int pm0 = tid >> 3, pj = tid & 7;
    const int ci0 = pm0 * MEM + bid * 8 + pj;
    const int ci1 = (pm0 + 32) * MEM + bid * 8 + pj;
    float creg0 = c_st[ci0], creg1 = c_st[ci1];

    // initial Zx[0] prefetch
#pragma unroll
    for (int i = 0; i < 2; i++) cpa16(zx_dst[i], g_Zx + zx_soff[i]);
    cpa_commit();
    __syncthreads();   // W_s ready

    for (int t = 0; t < TT; t++) {
        const float* hr = g_h2[layer][t & 1];
        float* hw = g_h2[layer][(t + 1) & 1];

        // prologue: chunks 0,1 in one group
#pragma unroll
        for (int i = 0; i < 4; i++) cpa16(a_dst[i], hr + a_soff[i]);
#pragma unroll
        for (int i = 0; i < 4; i++) cpa16(a_dst[i] + 16384u, hr + a_soff[i] + 16);
        cpa_commit();

        float acc[2][4][4];
#pragma unroll
        for (int mt = 0; mt < 2; mt++)
#pragma unroll
            for (int nt = 0; nt < 4; nt++)
#pragma unroll
                for (int q = 0; q < 4; q++) acc[mt][nt][q] = 0.0f;

        for (int s = 0; s < 8; s++) {
            WAITG(0);
            __syncthreads();
            if (s < 7) {
                const float* src0 = hr + (2 * s + 2) * 16;
                uint32_t bo2 = (uint32_t)((2 * s + 2) & 3) * 16384u;
                uint32_t bo3 = (uint32_t)((2 * s + 3) & 3) * 16384u;
#pragma unroll
                for (int i = 0; i < 4; i++) cpa16(a_dst[i] + bo2, src0 + a_soff[i]);
#pragma unroll
                for (int i = 0; i < 4; i++) cpa16(a_dst[i] + bo3, src0 + a_soff[i] + 16);
                cpa_commit();
            }
#pragma unroll
            for (int half = 0; half < 2; half++) {
                int kc = 2 * s + half;
                const float* Ab = As_ + (kc & 3) * 4096;
#pragma unroll
                for (int kk = 0; kk < 2; kk++) {
                    int kl0 = (kk * 8 + tig) ^ fA;
                    int kl1 = (kk * 8 + tig + 4) ^ fA;
                    uint32_t a[2][4];
#pragma unroll
                    for (int mt = 0; mt < 2; mt++) {
                        a[mt][0] = fu(Ab[a_base[mt] + kl0]);
                        a[mt][1] = fu(Ab[a_base[mt] + 128 + kl0]);
                        a[mt][2] = fu(Ab[a_base[mt] + kl1]);
                        a[mt][3] = fu(Ab[a_base[mt] + 128 + kl1]);
                    }
                    int kg = kq * 256 + kc * 16 + kk * 8 + tig;
#pragma unroll
                    for (int nt = 0; nt < 4; nt++) {
                        uint32_t b0 = fu(W_s[b_nidx[nt] + (kg ^ swzB)]);
                        uint32_t b1 = fu(W_s[b_nidx[nt] + ((kg + 4) ^ swzB)]);
#pragma unroll
                        for (int mt = 0; mt < 2; mt++)
                            mma8(acc[mt][nt], a[mt][0], a[mt][1], a[mt][2], a[mt][3], b0, b1);
                    }
                }
            }
        }
        __syncthreads();   // all buffers consumed; Zs aliases buffers 0-2

        // store split-K partials
#pragma unroll
        for (int mt = 0; mt < 2; mt++) {
            int row = wm * 32 + mt * 16 + gid;
#pragma unroll
            for (int nt = 0; nt < 4; nt++) {
                int col = nt * 8 + tig * 2;
                *(float2*)&Zs[kq * 2304 + row * 36 + col] =
                    make_float2(acc[mt][nt][0], acc[mt][nt][1]);
                *(float2*)&Zs[kq * 2304 + (row + 8) * 36 + col] =
                    make_float2(acc[mt][nt][2], acc[mt][nt][3]);
            }
        }
        __syncthreads();

        // pointwise
#pragma unroll
        for (int e = 0; e < 2; e++) {
            int m = pm0 + e * 32;
            int ci = e ? ci1 : ci0;
            float4 z = *(const float4*)&Zx_s[m * 36 + pj * 4];
#pragma unroll
            for (int q = 0; q < 4; q++) {
                float4 p = *(const float4*)&Zs[q * 2304 + m * 36 + pj * 4];
                z.x += p.x; z.y += p.y; z.z += p.z; z.w += p.w;
            }
            float c = e ? creg1 : creg0;
            float cn = c * sigm(z.z + 1.0f) + sigm(z.x) * tanhf(z.y);
            float hn = tanhf(cn) * sigm(z.w);
            if (e) creg1 = cn; else creg0 = cn;
            hw[ci] = to_tf32(hn);
            g_hall[(size_t)t * BB * MEM + ci] = hn;
            if (t == TT - 1) g_hfin[layer][ci] = hn;
        }
        __syncthreads();   // Zx_s free; Zs free

        if (t + 1 < TT) {
            // prefetch Zx[t+1] (independent of h) — hides under the barrier
            const float* zxn = g_Zx + (size_t)(t + 1) * BB * G4;
#pragma unroll
            for (int i = 0; i < 2; i++) cpa16(zx_dst[i], zxn + zx_soff[i]);
            cpa_commit();

            // grid barrier (no trailing fence: next-step h reads go through L2 via cp.async.cg)
            int want = ep_base + t + 1;
            if (tid == 0) {
                __threadfence();
                g_arrive[bid] = want;
            }
            if (tid < 128) {
                while (g_arrive[tid] < want) { }
            }
            __syncthreads();
        }
    }

    c_st[ci0] = creg0;
    c_st[ci1] = creg1;
}

// ---------------- pack final_state [2, B, 2*MEM] ----------------
__global__ void state_pack(float* __restrict__ out)
{
    int i = blockIdx.x * 256 + threadIdx.x;
    int l = i / (BB * 2 * MEM);
    int rem = i % (BB * 2 * MEM);
    int b = rem / (2 * MEM);
    int u = rem % (2 * MEM);
    out[i] = (u < MEM) ? g_c[l][b * MEM + u] : g_hfin[l][b * MEM + (u - MEM)];
}

extern "C" void kernel_launch(void* const* d_in, const int* in_sizes, int n_in,
                              void* d_out, int out_size)
{
    const float* x    = (const float*)d_in[0];
    const float* s0   = (const float*)d_in[1];
    const float* s1   = (const float*)d_in[2];
    const float* W0   = (const float*)d_in[3];
    const float* b0   = (const float*)d_in[4];
    const float* W1   = (const float*)d_in[5];
    const float* b1   = (const float*)d_in[6];
    const float* Wout = (const float*)d_in[7];
    const float* bout = (const float*)d_in[8];
    float* out = (float*)d_out;

    const int LSTM_SMEM = SM_TOTAL_F * 4;   // 205824 B
    cudaFuncSetAttribute(lstm_layer_persist,
                         cudaFuncAttributeMaxDynamicSharedMemorySize, LSTM_SMEM);

    init_state<<<256, 256>>>(s0, s1);

    {
        size_t total = (size_t)(VV + MEM) * MEM + (size_t)(2 * MEM) * MEM;
        int blocks = (int)((total + 255) / 256);
        permute_w<<<blocks, 256>>>(W0, b0, W1, b1);
    }
    transpose_w2<<<dim3((VV + MEM) / 32, G4 / 32), 256>>>(W0, 0);
    transpose_w2<<<dim3((2 * MEM) / 32, G4 / 32), 256>>>(W1, 1);
    transpose_wout<<<dim3(MEM / 32, VV / 32), 256>>>(Wout);

    // Phase 1: Zx = x @ W0[:256,:] + b0   (M=32768, N=4096, K=256)
    gemm_mma<<<dim3(64, 256), 256>>>(x, (long)TT * VV, (long)VV,
                                     (long)(VV + MEM), VV, 0, 0,
                                     nullptr, nullptr, (long)G4, (long)BB * G4);

    // Layer 0 recurrence
    lstm_layer_persist<<<128, 256, LSTM_SMEM>>>(0, 0);

    // Phase 3: Zx = h0_all @ W1[:1024,:] + b1   (M=32768, N=4096, K=1024)
    gemm_mma<<<dim3(64, 256), 256>>>(nullptr, (long)MEM, (long)BB * MEM,
                                     (long)(2 * MEM), MEM, 1, 1,
                                     nullptr, nullptr, (long)G4, (long)BB * G4);

    // Layer 1 recurrence
    lstm_layer_persist<<<128, 256, LSTM_SMEM>>>(1, TT);

    // Phase 5 (tf32 mma): out[b,t,:] = h1_all @ W_out + b_out   (M=32768, N=256, K=1024)
    gemm_mma<<<dim3(4, 256), 256>>>(nullptr, (long)MEM, (long)BB * MEM,
                                    (long)MEM, MEM, 1, 2,
                                    out, bout, (long)TT * VV, (long)VV);

    state_pack<<<1024, 256>>>(out + (size_t)BB * TT * VV);
}

// round 9
// speedup vs baseline: 3.2287x; 1.2077x over previous
#include <cuda_runtime.h>
#include <cuda_fp16.h>
#include <math.h>
#include <stdint.h>

#define BB 64
#define TT 512
#define VV 256
#define MEM 1024
#define G4 4096

// ---------------- device scratch ----------------
__device__ float g_Zx[(size_t)TT * BB * G4];            // input-side z (+bias), gate-permuted cols, fp32
__device__ float g_hall[(size_t)TT * BB * MEM];         // per-layer h sequence fp32 (reused)
__device__ float g_c[2][BB * MEM];                      // cell state per layer, fp32
__device__ uint32_t g_h2[2][2][BB * 512];               // h state as packed half2 (pairs along k), double-buffered
__device__ float g_hfin[2][BB * MEM];                   // final-step h, fp32
__device__ uint32_t g_W0h[((VV + MEM) / 2) * G4];       // W0 packed half2 pairs along k, gate-permuted cols
__device__ uint32_t g_W1h[((2 * MEM) / 2) * G4];        // W1 same
__device__ __half g_W0t[(size_t)G4 * (VV + MEM)];       // W0^T [n][k] halves, gate-permuted n
__device__ __half g_W1t[(size_t)G4 * (2 * MEM)];        // W1^T
__device__ __half g_Wot[(size_t)VV * MEM];              // W_out^T [n][k] halves
__device__ float g_b0p[G4];
__device__ float g_b1p[G4];
__device__ volatile int g_arrive[128];

__device__ __forceinline__ float sigm(float x) { return 1.0f / (1.0f + expf(-x)); }
__device__ __forceinline__ uint32_t pk(float a, float b) {
    __half2 h = __floats2half2_rn(a, b);
    return *(uint32_t*)&h;
}
__device__ __forceinline__ uint32_t smem_u32(const void* p) {
    uint32_t a;
    asm("{ .reg .u64 t; cvta.to.shared.u64 t, %1; cvt.u32.u64 %0, t; }" : "=r"(a) : "l"(p));
    return a;
}
__device__ __forceinline__ void cpa16(uint32_t dst, const void* src) {
    asm volatile("cp.async.cg.shared.global [%0], [%1], 16;" :: "r"(dst), "l"(src));
}
__device__ __forceinline__ void cpa_commit() { asm volatile("cp.async.commit_group;" ::: "memory"); }
#define WAITG(n) asm volatile("cp.async.wait_group %0;" :: "n"(n) : "memory")

// m16n8k16 fp16 mma, fp32 accum
__device__ __forceinline__ void mma16(float* d, uint32_t a0, uint32_t a1, uint32_t a2, uint32_t a3,
                                      uint32_t b0, uint32_t b1) {
    asm volatile("mma.sync.aligned.m16n8k16.row.col.f32.f16.f16.f32 "
                 "{%0,%1,%2,%3}, {%4,%5,%6,%7}, {%8,%9}, {%0,%1,%2,%3};"
                 : "+f"(d[0]), "+f"(d[1]), "+f"(d[2]), "+f"(d[3])
                 : "r"(a0), "r"(a1), "r"(a2), "r"(a3), "r"(b0), "r"(b1));
}

// ---------------- init: states (c fp32, h packed half2) + barrier flags ----------------
__global__ void init_state(const float* __restrict__ s0, const float* __restrict__ s1) {
    int i = blockIdx.x * 256 + threadIdx.x;     // 0 .. BB*MEM-1
    int b = i >> 10, u = i & 1023;
    g_c[0][i] = s0[b * 2 * MEM + u];
    g_c[1][i] = s1[b * 2 * MEM + u];
    if (u < 512) {
        int kp = u;
        g_h2[0][0][b * 512 + kp] = pk(s0[b * 2 * MEM + MEM + 2 * kp], s0[b * 2 * MEM + MEM + 2 * kp + 1]);
        g_h2[1][0][b * 512 + kp] = pk(s1[b * 2 * MEM + MEM + 2 * kp], s1[b * 2 * MEM + MEM + 2 * kp + 1]);
    }
    if (blockIdx.x == 0 && threadIdx.x < 128) g_arrive[threadIdx.x] = 0;
}

// ---------------- gate-permuted packed-half2 K-major weights + fp32 permuted biases ----------------
__global__ void permute_w(const float* __restrict__ W0, const float* __restrict__ b0,
                          const float* __restrict__ W1, const float* __restrict__ b1) {
    size_t i = (size_t)blockIdx.x * 256 + threadIdx.x;
    const size_t n0 = (size_t)((VV + MEM) / 2) * MEM;   // (kp,u) pairs for W0
    const size_t n1 = (size_t)((2 * MEM) / 2) * MEM;
    if (i < n0) {
        size_t kp = i >> 10; int u = (int)(i & 1023);
        const float* s = W0 + (size_t)(2 * kp) * G4 + u;
        uint4 v;
        v.x = pk(s[0],    s[G4]);
        v.y = pk(s[1024], s[G4 + 1024]);
        v.z = pk(s[2048], s[G4 + 2048]);
        v.w = pk(s[3072], s[G4 + 3072]);
        *(uint4*)&g_W0h[kp * G4 + (size_t)u * 4] = v;
    } else if (i < n0 + n1) {
        size_t k = i - n0;
        size_t kp = k >> 10; int u = (int)(k & 1023);
        const float* s = W1 + (size_t)(2 * kp) * G4 + u;
        uint4 v;
        v.x = pk(s[0],    s[G4]);
        v.y = pk(s[1024], s[G4 + 1024]);
        v.z = pk(s[2048], s[G4 + 2048]);
        v.w = pk(s[3072], s[G4 + 3072]);
        *(uint4*)&g_W1h[kp * G4 + (size_t)u * 4] = v;
    }
    if (i < MEM) {
        int u = (int)i;
        float4 vb0 = { b0[u], b0[1024 + u], b0[2048 + u], b0[3072 + u] };
        float4 vb1 = { b1[u], b1[1024 + u], b1[2048 + u], b1[3072 + u] };
        *(float4*)&g_b0p[u * 4] = vb0;
        *(float4*)&g_b1p[u * 4] = vb1;
    }
}

// ---------------- transposed half weights WT[n][k] (gate-permuted n) ----------------
__global__ __launch_bounds__(256) void transpose_w2(const float* __restrict__ W, int sel) {
    __shared__ float s[32][33];
    int tx = threadIdx.x & 31, ty = threadIdx.x >> 5;
    int k0 = blockIdx.x * 32, c0 = blockIdx.y * 32;
    __half* dst = (sel == 0) ? g_W0t : g_W1t;
    long wst = (sel == 0) ? (VV + MEM) : (2 * MEM);
#pragma unroll
    for (int j = 0; j < 4; j++)
        s[ty + j * 8][tx] = W[(size_t)(k0 + ty + j * 8) * G4 + c0 + tx];
    __syncthreads();
#pragma unroll
    for (int j = 0; j < 4; j++) {
        int c = c0 + ty + j * 8;
        int n = (c & 1023) * 4 + (c >> 10);
        dst[(size_t)n * wst + k0 + tx] = __float2half_rn(s[tx][ty + j * 8]);
    }
}

__global__ __launch_bounds__(256) void transpose_wout(const float* __restrict__ W) {
    __shared__ float s[32][33];
    int tx = threadIdx.x & 31, ty = threadIdx.x >> 5;
    int k0 = blockIdx.x * 32, c0 = blockIdx.y * 32;
#pragma unroll
    for (int j = 0; j < 4; j++)
        s[ty + j * 8][tx] = W[(size_t)(k0 + ty + j * 8) * VV + c0 + tx];
    __syncthreads();
#pragma unroll
    for (int j = 0; j < 4; j++) {
        int n = c0 + ty + j * 8;
        g_Wot[(size_t)n * MEM + k0 + tx] = __float2half_rn(s[tx][ty + j * 8]);
    }
}

// ---------------- fp16 mma GEMM: C[r, bcol..] = bias + A[r,:K] @ W[:K, bcol..] ----------------
// block 128x64, 8 warps (4m x 2n) of 32x32. k-tile = 64 halves (32 pairs). XOR-swizzled smem.
__global__ __launch_bounds__(256) void gemm_mma(
    const float* __restrict__ Ain, long sb, long st,
    long wst, int K, int src_gh, int w_sel,
    float* __restrict__ Cout, const float* __restrict__ bias_ext,
    long ocb, long oct)
{
    const float* A = src_gh ? (const float*)g_hall : Ain;
    const __half* WT = (w_sel == 0) ? g_W0t : ((w_sel == 1) ? g_W1t : g_Wot);
    const float* bias = (w_sel == 0) ? g_b0p : ((w_sel == 1) ? g_b1p : bias_ext);
    float* C = (w_sel == 2) ? Cout : (float*)g_Zx;

    __shared__ uint32_t As[128 * 32];   // [row][pair^swz], 16KB
    __shared__ uint32_t Bs[64 * 32];    // [n][pair^swz], 8KB

    const int tid = threadIdx.x;
    const int wid = tid >> 5, lane = tid & 31;
    const int gid = lane >> 2, tig = lane & 3;
    const int wm = wid & 3, wn = wid >> 2;
    const long brow = (long)blockIdx.y * 128;
    const int bcol = blockIdx.x * 64;

    int a_sw[4];
    const float* a_ptr[4];
#pragma unroll
    for (int i = 0; i < 4; i++) {
        int f = tid + i * 256;
        int row = f >> 3, g4 = f & 7;
        a_sw[i] = row * 32 + ((g4 * 4) ^ ((row & 7) * 4));
        long r = brow + row;
        a_ptr[i] = A + (r & 63) * sb + (r >> 6) * st + g4 * 8;
    }
    int b_sw[2];
    const uint32_t* b_ptr[2];
#pragma unroll
    for (int i = 0; i < 2; i++) {
        int f = tid + i * 256;
        int n = f >> 3, g4 = f & 7;
        b_sw[i] = n * 32 + ((g4 * 4) ^ ((n & 7) * 4));
        b_ptr[i] = (const uint32_t*)(WT + (size_t)(bcol + n) * wst) + g4 * 4;
    }

    float acc[2][4][4];
#pragma unroll
    for (int mt = 0; mt < 2; mt++)
#pragma unroll
        for (int nt = 0; nt < 4; nt++)
#pragma unroll
            for (int q = 0; q < 4; q++) acc[mt][nt][q] = 0.0f;

    const int arow0 = wm * 32 + gid;
    const int nb0 = wn * 32 + gid;
    const int xg = gid * 4;

    for (int kb = 0; kb < K; kb += 64) {
        float4 alo[4], ahi[4];
        uint4 bv[2];
#pragma unroll
        for (int i = 0; i < 4; i++) {
            alo[i] = *(const float4*)(a_ptr[i] + kb);
            ahi[i] = *(const float4*)(a_ptr[i] + kb + 4);
        }
#pragma unroll
        for (int i = 0; i < 2; i++) bv[i] = *(const uint4*)(b_ptr[i] + kb / 2);
        __syncthreads();
#pragma unroll
        for (int i = 0; i < 4; i++) {
            uint4 v;
            v.x = pk(alo[i].x, alo[i].y);
            v.y = pk(alo[i].z, alo[i].w);
            v.z = pk(ahi[i].x, ahi[i].y);
            v.w = pk(ahi[i].z, ahi[i].w);
            *(uint4*)&As[a_sw[i]] = v;
        }
#pragma unroll
        for (int i = 0; i < 2; i++) *(uint4*)&Bs[b_sw[i]] = bv[i];
        __syncthreads();

#pragma unroll
        for (int ks = 0; ks < 4; ks++) {
            int p0 = (ks * 8 + tig) ^ xg;
            int p1 = (ks * 8 + tig + 4) ^ xg;
            uint32_t a[2][4];
#pragma unroll
            for (int mt = 0; mt < 2; mt++) {
                int r0 = (arow0 + mt * 16) * 32;
                a[mt][0] = As[r0 + p0];
                a[mt][1] = As[r0 + 256 + p0];
                a[mt][2] = As[r0 + p1];
                a[mt][3] = As[r0 + 256 + p1];
            }
#pragma unroll
            for (int nt = 0; nt < 4; nt++) {
                int n = (nb0 + nt * 8) * 32;
                uint32_t b0 = Bs[n + p0];
                uint32_t b1 = Bs[n + p1];
#pragma unroll
                for (int mt = 0; mt < 2; mt++)
                    mma16(acc[mt][nt], a[mt][0], a[mt][1], a[mt][2], a[mt][3], b0, b1);
            }
        }
        __syncthreads();
    }

#pragma unroll
    for (int mt = 0; mt < 2; mt++) {
        long r2 = brow + wm * 32 + mt * 16 + gid;
        long co0 = (r2 & 63) * ocb + (r2 >> 6) * oct;
        long r3 = r2 + 8;
        long co1 = (r3 & 63) * ocb + (r3 >> 6) * oct;
#pragma unroll
        for (int nt = 0; nt < 4; nt++) {
            int col = bcol + wn * 32 + nt * 8 + tig * 2;
            float bz0 = bias[col], bz1 = bias[col + 1];
            float2 v0 = { acc[mt][nt][0] + bz0, acc[mt][nt][1] + bz1 };
            float2 v1 = { acc[mt][nt][2] + bz0, acc[mt][nt][3] + bz1 };
            *(float2*)(C + co0 + col) = v0;
            *(float2*)(C + co1 + col) = v1;
        }
    }
}

// ---------------- persistent recurrence, fp16 mma ----------------
// smem bytes: W_s [0,65536) u32[32][512] | As 4x8192 [65536,98304) | Zs [98304,135168) | Zx [135168,144384)
#define SMB_AS 65536
#define SMB_ZS 98304
#define SMB_ZX 135168
#define SMB_TOTAL 144384

__global__ __launch_bounds__(256) void lstm_layer_persist(int layer, int ep_base)
{
    extern __shared__ char dynraw[];
    uint32_t* W_s = (uint32_t*)dynraw;                 // [n][kp^swz], 32 x 512
    uint32_t* As_ = (uint32_t*)(dynraw + SMB_AS);      // 4 chunk buffers x 2048 u32
    float* Zs  = (float*)(dynraw + SMB_ZS);            // [q4][64][36]
    float* Zx_s = (float*)(dynraw + SMB_ZX);           // [64][36]

    const uint32_t* Wh = (layer == 0) ? (g_W0h + (size_t)(VV / 2) * G4)
                                      : (g_W1h + (size_t)(MEM / 2) * G4);
    float* c_st = g_c[layer];
    const int bid = blockIdx.x;
    const int tid = threadIdx.x;
    const int n0 = bid * 32;

    const int wid = tid >> 5, lane = tid & 31;
    const int gid = lane >> 2, tig = lane & 3;
    const int kq = wid & 3;           // k quarter (128 pairs)
    const int wm = wid >> 2;          // m half (32 rows)
    const int xg = gid * 4;

    // preload W slice [32 n][512 kp], swizzled
    for (int idx = tid; idx < 32 * 512; idx += 256) {
        int kp = idx >> 5, n = idx & 31;
        W_s[n * 512 + (kp ^ ((n & 7) * 4))] = Wh[(size_t)kp * G4 + n0 + n];
    }

    const uint32_t sbase = smem_u32(dynraw);

    // h-chunk staging: granule g = tid + i*256 (i<2): q=g>>7, row=(g>>1)&63, k4=g&1
    uint32_t a_dst[2]; int a_soff[2];
#pragma unroll
    for (int i = 0; i < 2; i++) {
        int g = tid + i * 256;
        int q = g >> 7, row = (g >> 1) & 63, k4 = g & 1;
        a_dst[i] = sbase + (uint32_t)SMB_AS + (uint32_t)(row * 32 + ((q * 8 + k4 * 4) ^ ((row & 7) * 4))) * 4u;
        a_soff[i] = row * 512 + q * 128 + k4 * 4;    // u32 units in h row (512 pairs)
    }
    // Zx staging (fp32, stride 36): g = tid + i*256: m=g>>3, c4=g&7
    uint32_t zx_dst[2]; int zx_soff[2];
#pragma unroll
    for (int i = 0; i < 2; i++) {
        int g = tid + i * 256;
        int m = g >> 3, c4 = g & 7;
        zx_dst[i] = sbase + (uint32_t)SMB_ZX + (uint32_t)(m * 36 + c4 * 4) * 4u;
        zx_soff[i] = m * G4 + n0 + c4 * 4;
    }

    // fragment constants
    int a_base[2];
#pragma unroll
    for (int mt = 0; mt < 2; mt++)
        a_base[mt] = (wm * 32 + mt * 16 + gid) * 32;
    int b_nidx[4];
#pragma unroll
    for (int nt = 0; nt < 4; nt++)
        b_nidx[nt] = (nt * 8 + gid) * 512;

    // pointwise constants + c registers
    const int pm0 = tid >> 3, pj = tid & 7;
    const int ci0 = pm0 * MEM + bid * 8 + pj;
    const int ci1 = (pm0 + 32) * MEM + bid * 8 + pj;
    float creg0 = c_st[ci0], creg1 = c_st[ci1];

    // initial Zx[0] prefetch
#pragma unroll
    for (int i = 0; i < 2; i++) cpa16(zx_dst[i], g_Zx + zx_soff[i]);
    cpa_commit();
    __syncthreads();   // W_s ready

    for (int t = 0; t < TT; t++) {
        const uint32_t* hr = g_h2[layer][t & 1];
        __half* hw_h = (__half*)g_h2[layer][(t + 1) & 1];

        // prologue: chunks 0,1 in one group
#pragma unroll
        for (int i = 0; i < 2; i++) cpa16(a_dst[i], hr + a_soff[i]);
#pragma unroll
        for (int i = 0; i < 2; i++) cpa16(a_dst[i] + 8192u, hr + a_soff[i] + 8);
        cpa_commit();

        float acc[2][4][4];
#pragma unroll
        for (int mt = 0; mt < 2; mt++)
#pragma unroll
            for (int nt = 0; nt < 4; nt++)
#pragma unroll
                for (int q = 0; q < 4; q++) acc[mt][nt][q] = 0.0f;

        for (int s = 0; s < 8; s++) {
            WAITG(0);
            __syncthreads();
            if (s < 7) {
                const uint32_t* src0 = hr + (2 * s + 2) * 8;
                uint32_t bo2 = (uint32_t)((2 * s + 2) & 3) * 8192u;
                uint32_t bo3 = (uint32_t)((2 * s + 3) & 3) * 8192u;
#pragma unroll
                for (int i = 0; i < 2; i++) cpa16(a_dst[i] + bo2, src0 + a_soff[i]);
#pragma unroll
                for (int i = 0; i < 2; i++) cpa16(a_dst[i] + bo3, src0 + a_soff[i] + 8);
                cpa_commit();
            }
#pragma unroll
            for (int half = 0; half < 2; half++) {
                int kc = 2 * s + half;
                const uint32_t* Ab = As_ + (kc & 3) * 2048;
                int p0 = (kq * 8 + tig) ^ xg;
                int p1 = (kq * 8 + tig + 4) ^ xg;
                uint32_t a[2][4];
#pragma unroll
                for (int mt = 0; mt < 2; mt++) {
                    a[mt][0] = Ab[a_base[mt] + p0];
                    a[mt][1] = Ab[a_base[mt] + 256 + p0];
                    a[mt][2] = Ab[a_base[mt] + p1];
                    a[mt][3] = Ab[a_base[mt] + 256 + p1];
                }
                int kp0 = kq * 128 + kc * 8 + tig;
#pragma unroll
                for (int nt = 0; nt < 4; nt++) {
                    uint32_t b0 = W_s[b_nidx[nt] + (kp0 ^ xg)];
                    uint32_t b1 = W_s[b_nidx[nt] + ((kp0 + 4) ^ xg)];
#pragma unroll
                    for (int mt = 0; mt < 2; mt++)
                        mma16(acc[mt][nt], a[mt][0], a[mt][1], a[mt][2], a[mt][3], b0, b1);
                }
            }
        }
        __syncthreads();

        // store split-K partials (fp32)
#pragma unroll
        for (int mt = 0; mt < 2; mt++) {
            int row = wm * 32 + mt * 16 + gid;
#pragma unroll
            for (int nt = 0; nt < 4; nt++) {
                int col = nt * 8 + tig * 2;
                *(float2*)&Zs[kq * 2304 + row * 36 + col] =
                    make_float2(acc[mt][nt][0], acc[mt][nt][1]);
                *(float2*)&Zs[kq * 2304 + (row + 8) * 36 + col] =
                    make_float2(acc[mt][nt][2], acc[mt][nt][3]);
            }
        }
        __syncthreads();

        // pointwise
#pragma unroll
        for (int e = 0; e < 2; e++) {
            int m = pm0 + e * 32;
            int ci = e ? ci1 : ci0;
            float4 z = *(const float4*)&Zx_s[m * 36 + pj * 4];
#pragma unroll
            for (int q = 0; q < 4; q++) {
                float4 p = *(const float4*)&Zs[q * 2304 + m * 36 + pj * 4];
                z.x += p.x; z.y += p.y; z.z += p.z; z.w += p.w;
            }
            float c = e ? creg1 : creg0;
            float cn = c * sigm(z.z + 1.0f) + sigm(z.x) * tanhf(z.y);
            float hn = tanhf(cn) * sigm(z.w);
            if (e) creg1 = cn; else creg0 = cn;
            hw_h[m * MEM + bid * 8 + pj] = __float2half_rn(hn);
            g_hall[(size_t)t * BB * MEM + ci] = hn;
            if (t == TT - 1) g_hfin[layer][ci] = hn;
        }
        __syncthreads();

        if (t + 1 < TT) {
            const float* zxn = g_Zx + (size_t)(t + 1) * BB * G4;
#pragma unroll
            for (int i = 0; i < 2; i++) cpa16(zx_dst[i], zxn + zx_soff[i]);
            cpa_commit();

            int want = ep_base + t + 1;
            if (tid == 0) {
                __threadfence();
                g_arrive[bid] = want;
            }
            if (tid < 128) {
                while (g_arrive[tid] < want) { }
            }
            __syncthreads();
        }
    }

    c_st[ci0] = creg0;
    c_st[ci1] = creg1;
}

// ---------------- pack final_state [2, B, 2*MEM] ----------------
__global__ void state_pack(float* __restrict__ out)
{
    int i = blockIdx.x * 256 + threadIdx.x;
    int l = i / (BB * 2 * MEM);
    int rem = i % (BB * 2 * MEM);
    int b = rem / (2 * MEM);
    int u = rem % (2 * MEM);
    out[i] = (u < MEM) ? g_c[l][b * MEM + u] : g_hfin[l][b * MEM + (u - MEM)];
}

extern "C" void kernel_launch(void* const* d_in, const int* in_sizes, int n_in,
                              void* d_out, int out_size)
{
    const float* x    = (const float*)d_in[0];
    const float* s0   = (const float*)d_in[1];
    const float* s1   = (const float*)d_in[2];
    const float* W0   = (const float*)d_in[3];
    const float* b0   = (const float*)d_in[4];
    const float* W1   = (const float*)d_in[5];
    const float* b1   = (const float*)d_in[6];
    const float* Wout = (const float*)d_in[7];
    const float* bout = (const float*)d_in[8];
    float* out = (float*)d_out;

    cudaFuncSetAttribute(lstm_layer_persist,
                         cudaFuncAttributeMaxDynamicSharedMemorySize, SMB_TOTAL);

    init_state<<<256, 256>>>(s0, s1);

    {
        size_t total = (size_t)((VV + MEM) / 2) * MEM + (size_t)MEM * MEM;
        int blocks = (int)((total + 255) / 256);
        permute_w<<<blocks, 256>>>(W0, b0, W1, b1);
    }
    transpose_w2<<<dim3((VV + MEM) / 32, G4 / 32), 256>>>(W0, 0);
    transpose_w2<<<dim3((2 * MEM) / 32, G4 / 32), 256>>>(W1, 1);
    transpose_wout<<<dim3(MEM / 32, VV / 32), 256>>>(Wout);

    // Phase 1: Zx = x @ W0[:256,:] + b0   (M=32768, N=4096, K=256)
    gemm_mma<<<dim3(64, 256), 256>>>(x, (long)TT * VV, (long)VV,
                                     (long)(VV + MEM), VV, 0, 0,
                                     nullptr, nullptr, (long)G4, (long)BB * G4);

    // Layer 0 recurrence
    lstm_layer_persist<<<128, 256, SMB_TOTAL>>>(0, 0);

    // Phase 3: Zx = h0_all @ W1[:1024,:] + b1   (M=32768, N=4096, K=1024)
    gemm_mma<<<dim3(64, 256), 256>>>(nullptr, (long)MEM, (long)BB * MEM,
                                     (long)(2 * MEM), MEM, 1, 1,
                                     nullptr, nullptr, (long)G4, (long)BB * G4);

    // Layer 1 recurrence
    lstm_layer_persist<<<128, 256, SMB_TOTAL>>>(1, TT);

    // Phase 5: out[b,t,:] = h1_all @ W_out + b_out   (M=32768, N=256, K=1024)
    gemm_mma<<<dim3(4, 256), 256>>>(nullptr, (long)MEM, (long)BB * MEM,
                                    (long)MEM, MEM, 1, 2,
                                    out, bout, (long)TT * VV, (long)VV);

    state_pack<<<1024, 256>>>(out + (size_t)BB * TT * VV);
}